// round 6
// baseline (speedup 1.0000x reference)
#include <cuda_runtime.h>
#include <math.h>

#define TT 200
#define BB 128
#define FH 1024
#define PH 320
#define JH 512
#define VV 29
#define BLANKV 28
#define NSTEP 400
#define MAXL 256
#define YSN (NSTEP*BB*VV)

// ---------------- device scratch (no runtime allocation) ----------------
__device__ float  g_Fproj[(size_t)TT*BB*JH];   // f @ w_f + b_j
__device__ float4 g_xg0[VV*PH];                // embed@w_ih0+b0, [v][p][gate]
__device__ float4 g_wA [PH*PH];                // w_hh0 [k][p][gate]
__device__ float4 g_wB1[PH*PH];                // w_ih1 [k][p][gate]
__device__ float4 g_wB2[PH*PH];                // w_hh1 [k][p][gate]
__device__ float4 g_b1r[PH];                   // b1 [p][gate]

__device__ float g_h0[BB*PH], g_c0[BB*PH], g_h1[BB*PH], g_c1[BB*PH];
__device__ float g_h0n[BB*PH], g_c0n[BB*PH], g_h1n[BB*PH], g_c1n[BB*PH];
__device__ float g_jrelu[BB*JH];
__device__ int g_pre[BB], g_time[BB], g_olen[BB];
__device__ int g_tok[BB*MAXL];
__device__ unsigned g_eq[NSTEP];
__device__ unsigned g_gcnt[4], g_grel[4], g_bcnt, g_brel;

__device__ __forceinline__ float sigf(float x){ return 1.0f/(1.0f+expf(-x)); }

// monotonic-counter barrier over n CTAs (one arrival per CTA)
__device__ __forceinline__ void barwait(unsigned* cnt, unsigned* rel, unsigned n){
    __syncthreads();
    if (threadIdx.x == 0){
        __threadfence();
        unsigned a = atomicAdd(cnt, 1u) + 1u;
        if (a % n == 0u){
            atomicMax(rel, a);
        } else {
            unsigned tgt = ((a + n - 1u)/n)*n;
            while (*(volatile unsigned*)rel < tgt) __nanosleep(32);
        }
        __threadfence();   // gpu-scope: CCTL.IVALL -> L1D invalidated
    }
    __syncthreads();
}

// ---------------- init ----------------
__global__ void init_kernel(){
    int i = blockIdx.x*256 + threadIdx.x;
    if (i < BB*PH){ g_h0[i]=0.f; g_c0[i]=0.f; g_h1[i]=0.f; g_c1[i]=0.f; }
    if (i < BB){ g_pre[i]=0; g_time[i]=0; g_olen[i]=0; }
    if (i < BB*MAXL) g_tok[i] = BLANKV;
    if (i < NSTEP) g_eq[i] = 0u;
    if (i < 4){ g_gcnt[i]=0u; g_grel[i]=0u; }
    if (i == 0){ g_bcnt=0u; g_brel=0u; }
}

// ---------------- weight re-layout [k][4*PH gate-major] -> [k][p][gate] ----------------
__global__ void rearr_kernel(const float* __restrict__ w_hh0, const float* __restrict__ w_ih1,
                             const float* __restrict__ w_hh1, const float* __restrict__ b1){
    int i = blockIdx.x*256 + threadIdx.x;
    const int Nt = PH*PH*4;
    if (i < Nt){
        int g = i & 3, p = (i >> 2) % PH, k = i / (PH*4);
        int src = k*(4*PH) + g*PH + p;
        ((float*)g_wA )[i] = w_hh0[src];
        ((float*)g_wB1)[i] = w_ih1[src];
        ((float*)g_wB2)[i] = w_hh1[src];
    }
    if (i < PH*4){
        int g = i & 3, p = i >> 2;
        ((float*)g_b1r)[i] = b1[g*PH + p];
    }
}

// ---------------- xg0[v][p][g] = b0 + embed[v,:] @ w_ih0[:,g*PH+p] ----------------
__global__ void xg0_kernel(const float* __restrict__ embed, const float* __restrict__ w_ih0,
                           const float* __restrict__ b0v){
    __shared__ float es[PH];
    int v = blockIdx.x;
    for (int k = threadIdx.x; k < PH; k += 256) es[k] = embed[v*PH + k];
    __syncthreads();
    for (int j = threadIdx.x; j < PH*4; j += 256){
        int p = j >> 2, g = j & 3;
        float a = b0v[g*PH + p];
        const float* w = w_ih0 + g*PH + p;
        for (int k = 0; k < PH; k++) a = fmaf(es[k], w[k*(4*PH)], a);
        ((float*)g_xg0)[v*PH*4 + j] = a;
    }
}

// ---------------- Fproj = f(25600x1024) @ w_f(1024x512) + b_j ----------------
__global__ void __launch_bounds__(256) fproj_kernel(const float* __restrict__ A,
                                                    const float* __restrict__ Bm,
                                                    const float* __restrict__ bj){
    const int N = JH, K = FH;
    __shared__ float As[64][17];
    __shared__ float Bs[16][68];
    int bm = blockIdx.y*64, bn = blockIdx.x*64;
    int tid = threadIdx.x;
    int tx = tid & 15, ty = tid >> 4;
    float acc[4][4];
#pragma unroll
    for (int i = 0; i < 4; i++)
#pragma unroll
        for (int j = 0; j < 4; j++) acc[i][j] = 0.f;

    int lm = tid >> 2, lkq = tid & 3;
    int lk = tid >> 4, lnq = tid & 15;
    for (int k0 = 0; k0 < K; k0 += 16){
        float4 va = *(const float4*)(A + (size_t)(bm+lm)*K + k0 + lkq*4);
        As[lm][lkq*4+0]=va.x; As[lm][lkq*4+1]=va.y; As[lm][lkq*4+2]=va.z; As[lm][lkq*4+3]=va.w;
        float4 vb = *(const float4*)(Bm + (size_t)(k0+lk)*N + bn + lnq*4);
        Bs[lk][lnq*4+0]=vb.x; Bs[lk][lnq*4+1]=vb.y; Bs[lk][lnq*4+2]=vb.z; Bs[lk][lnq*4+3]=vb.w;
        __syncthreads();
#pragma unroll
        for (int k = 0; k < 16; k++){
            float a0=As[ty*4+0][k], a1=As[ty*4+1][k], a2=As[ty*4+2][k], a3=As[ty*4+3][k];
            float b0=Bs[k][tx*4+0], b1=Bs[k][tx*4+1], b2=Bs[k][tx*4+2], b3=Bs[k][tx*4+3];
            acc[0][0]=fmaf(a0,b0,acc[0][0]); acc[0][1]=fmaf(a0,b1,acc[0][1]);
            acc[0][2]=fmaf(a0,b2,acc[0][2]); acc[0][3]=fmaf(a0,b3,acc[0][3]);
            acc[1][0]=fmaf(a1,b0,acc[1][0]); acc[1][1]=fmaf(a1,b1,acc[1][1]);
            acc[1][2]=fmaf(a1,b2,acc[1][2]); acc[1][3]=fmaf(a1,b3,acc[1][3]);
            acc[2][0]=fmaf(a2,b0,acc[2][0]); acc[2][1]=fmaf(a2,b1,acc[2][1]);
            acc[2][2]=fmaf(a2,b2,acc[2][2]); acc[2][3]=fmaf(a2,b3,acc[2][3]);
            acc[3][0]=fmaf(a3,b0,acc[3][0]); acc[3][1]=fmaf(a3,b1,acc[3][1]);
            acc[3][2]=fmaf(a3,b2,acc[3][2]); acc[3][3]=fmaf(a3,b3,acc[3][3]);
        }
        __syncthreads();
    }
#pragma unroll
    for (int i = 0; i < 4; i++)
#pragma unroll
        for (int j = 0; j < 4; j++){
            int n = bn + tx*4 + j;
            g_Fproj[(size_t)(bm + ty*4 + i)*N + n] = acc[i][j] + bj[n];
        }
}

// ---------------- persistent decode: 128 CTAs x 320 threads ----------------
__global__ void __launch_bounds__(320,1)
decode_kernel(const int* __restrict__ f_lens, const float* __restrict__ w_g,
              const float* __restrict__ w_o, const float* __restrict__ b_o,
              float* __restrict__ out, int out_size){
    __shared__ float  sm_h[PH*33];      // h tile [k][b], padded stride 33 (42.2 KB)
    __shared__ float4 sm_w4[PH];        // weight chunk (5.1 KB); aliased as float in phase C
    __shared__ float  sm_y[32];
    __shared__ int    sm_nb;
    float* sm_wf = (float*)sm_w4;

    const int tid = threadIdx.x;
    const int cta = blockIdx.x;
    const int bb  = cta >> 5;           // batch block 0..3
    const int sub = cta & 31;           // p/j slice 0..31
    const int b0  = bb*32;
    const int bl  = tid & 31, pl = tid >> 5;   // batch lane, p-within-slice
    const int wkk = tid/10, wq = tid%10;       // weight-stage coords (phase A/B)
    const int myb = cta;                       // phase-D batch
    const int lane = tid & 31, wrp = tid >> 5; // phase-D

    for (int step = 0; step < NSTEP; step++){
        // ============ phase A: LSTM0 ============
        for (int e = tid; e < 32*PH; e += 320){
            int bi = e/PH, k = e - bi*PH;
            sm_h[k*33 + bi] = __ldcg(&g_h0[(b0+bi)*PH + k]);
        }
        __syncthreads();
        {
            const int p = sub*10 + pl;
            const int bgl = b0 + bl;
            int pre = __ldcg(&g_pre[bgl]);
            float4 acc = g_xg0[pre*PH + p];
            for (int k0 = 0; k0 < PH; k0 += 32){
                sm_w4[tid] = g_wA[(k0 + wkk)*PH + sub*10 + wq];
                __syncthreads();
#pragma unroll 8
                for (int k = 0; k < 32; k++){
                    float h = sm_h[(k0+k)*33 + bl];
                    float4 w = sm_w4[k*10 + pl];
                    acc.x = fmaf(h, w.x, acc.x); acc.y = fmaf(h, w.y, acc.y);
                    acc.z = fmaf(h, w.z, acc.z); acc.w = fmaf(h, w.w, acc.w);
                }
                __syncthreads();
            }
            float c  = __ldcg(&g_c0[bgl*PH + p]);
            float cn = sigf(acc.y)*c + sigf(acc.x)*tanhf(acc.z);
            float hn = sigf(acc.w)*tanhf(cn);
            __stcg(&g_c0n[bgl*PH + p], cn);
            __stcg(&g_h0n[bgl*PH + p], hn);
        }
        barwait(&g_gcnt[bb], &g_grel[bb], 32u);

        // ============ phase B: LSTM1 (K = 320 + 320) ============
        {
            const int p = sub*10 + pl;
            const int bgl = b0 + bl;
            float4 acc = g_b1r[p];
#pragma unroll 1
            for (int pass = 0; pass < 2; pass++){
                const float*  hin = pass ? g_h1  : g_h0n;
                const float4* W   = pass ? g_wB2 : g_wB1;
                for (int e = tid; e < 32*PH; e += 320){
                    int bi = e/PH, k = e - bi*PH;
                    sm_h[k*33 + bi] = __ldcg(&hin[(b0+bi)*PH + k]);
                }
                __syncthreads();
                for (int k0 = 0; k0 < PH; k0 += 32){
                    sm_w4[tid] = W[(k0 + wkk)*PH + sub*10 + wq];
                    __syncthreads();
#pragma unroll 8
                    for (int k = 0; k < 32; k++){
                        float h = sm_h[(k0+k)*33 + bl];
                        float4 w = sm_w4[k*10 + pl];
                        acc.x = fmaf(h, w.x, acc.x); acc.y = fmaf(h, w.y, acc.y);
                        acc.z = fmaf(h, w.z, acc.z); acc.w = fmaf(h, w.w, acc.w);
                    }
                    __syncthreads();
                }
            }
            float c  = __ldcg(&g_c1[bgl*PH + p]);
            float cn = sigf(acc.y)*c + sigf(acc.x)*tanhf(acc.z);
            float hn = sigf(acc.w)*tanhf(cn);
            __stcg(&g_c1n[bgl*PH + p], cn);
            __stcg(&g_h1n[bgl*PH + p], hn);
        }
        barwait(&g_gcnt[bb], &g_grel[bb], 32u);

        // ============ phase C: jrelu = relu(Fproj[time[b]] + h1n @ w_g) ============
        {
            const int bgl = b0 + bl;
            for (int e = tid; e < 32*PH; e += 320){
                int bi = e/PH, k = e - bi*PH;
                sm_h[k*33 + bi] = __ldcg(&g_h1n[(b0+bi)*PH + k]);
            }
            __syncthreads();
            float acc1 = 0.f, acc2 = 0.f;
            for (int k0 = 0; k0 < PH; k0 += 32){
                for (int e = tid; e < 32*16; e += 320)
                    sm_wf[e] = w_g[(size_t)(k0 + e/16)*JH + sub*16 + (e & 15)];
                __syncthreads();
#pragma unroll 8
                for (int k = 0; k < 32; k++){
                    float h = sm_h[(k0+k)*33 + bl];
                    acc1 = fmaf(h, sm_wf[k*16 + pl], acc1);
                    if (pl < 6) acc2 = fmaf(h, sm_wf[k*16 + pl + 10], acc2);
                }
                __syncthreads();
            }
            int t = __ldcg(&g_time[bgl]);
            size_t fb = ((size_t)t*BB + bgl)*JH + sub*16;
            float r1 = g_Fproj[fb + pl] + acc1;
            __stcg(&g_jrelu[bgl*JH + sub*16 + pl], r1 > 0.f ? r1 : 0.f);
            if (pl < 6){
                float r2 = g_Fproj[fb + pl + 10] + acc2;
                __stcg(&g_jrelu[bgl*JH + sub*16 + pl + 10], r2 > 0.f ? r2 : 0.f);
            }
        }
        barwait(&g_gcnt[bb], &g_grel[bb], 32u);

        // ============ phase D: logits + argmax + commit (CTA = batch) ============
        {
            for (int e = tid; e < JH; e += 320)
                sm_h[e] = __ldcg(&g_jrelu[myb*JH + e]);
            __syncthreads();
#pragma unroll
            for (int vi = 0; vi < 3; vi++){
                int v = wrp + vi*10;
                if (v < VV){
                    float a = 0.f;
#pragma unroll
                    for (int k = lane; k < JH; k += 32)
                        a = fmaf(sm_h[k], w_o[(size_t)k*VV + v], a);
#pragma unroll
                    for (int off = 16; off > 0; off >>= 1)
                        a += __shfl_xor_sync(0xffffffffu, a, off);
                    if (lane == 0) sm_y[v] = a + b_o[v];
                }
            }
            __syncthreads();
            // write ys[step][myb][:]
            if (tid < VV){
                int idx = (step*BB + myb)*VV + tid;
                if (idx < out_size) out[idx] = sm_y[tid];
            }
            if (tid == 0){
                int sym = 0; float best = sm_y[0];
                for (int v = 1; v < VV; v++) if (sm_y[v] > best){ best = sm_y[v]; sym = v; }
                int fin = (step > 0) && (__ldcg(&g_eq[step-1]) == (unsigned)BB);
                int nb  = (!fin) && (sym != BLANKV);
                int blk = (!fin) && (sym == BLANKV);
                if (nb){
                    int olen = g_olen[myb];
                    int pos = olen < (MAXL-1) ? olen : (MAXL-1);
                    g_tok[myb*MAXL + pos] = sym;
                    g_olen[myb] = olen + 1;
                    __stcg(&g_pre[myb], sym);
                }
                int tm  = __ldcg(&g_time[myb]);
                int eos = f_lens[myb] - 1;
                if (blk){ tm = tm + 1; if (tm > eos) tm = eos; }
                __stcg(&g_time[myb], tm);
                if (tm == eos) atomicAdd(&g_eq[step], 1u);
                sm_nb = nb;
            }
            __syncthreads();
            if (sm_nb){
                int i = myb*PH + tid;
                __stcg(&g_h0[i], __ldcg(&g_h0n[i]));
                __stcg(&g_c0[i], __ldcg(&g_c0n[i]));
                __stcg(&g_h1[i], __ldcg(&g_h1n[i]));
                __stcg(&g_c1[i], __ldcg(&g_c1n[i]));
            }
        }
        barwait(&g_bcnt, &g_brel, 128u);   // global: orders g_eq + all state for next step
    }

    // final: tokens + out_lens (cast to float), CTA = batch
    if (tid < MAXL){
        int idx = YSN + myb*MAXL + tid;
        if (idx < out_size) out[idx] = (float)g_tok[myb*MAXL + tid];
    }
    if (tid == 0){
        int idx = YSN + BB*MAXL + myb;
        if (idx < out_size) out[idx] = (float)g_olen[myb];
    }
}

extern "C" void kernel_launch(void* const* d_in, const int* in_sizes, int n_in,
                              void* d_out, int out_size){
    const float* f      = (const float*)d_in[0];
    const int*   f_lens = (const int*)  d_in[1];
    const float* embed  = (const float*)d_in[2];
    const float* w_ih0  = (const float*)d_in[3];
    const float* w_hh0  = (const float*)d_in[4];
    const float* b0     = (const float*)d_in[5];
    const float* w_ih1  = (const float*)d_in[6];
    const float* w_hh1  = (const float*)d_in[7];
    const float* b1     = (const float*)d_in[8];
    const float* w_f    = (const float*)d_in[9];
    const float* w_g    = (const float*)d_in[10];
    const float* b_j    = (const float*)d_in[11];
    const float* w_o    = (const float*)d_in[12];
    const float* b_o    = (const float*)d_in[13];
    float* out = (float*)d_out;

    init_kernel<<<160, 256>>>();
    rearr_kernel<<<1600, 256>>>(w_hh0, w_ih1, w_hh1, b1);
    xg0_kernel<<<VV, 256>>>(embed, w_ih0, b0);
    fproj_kernel<<<dim3(JH/64, (TT*BB)/64), 256>>>(f, w_f, b_j);
    decode_kernel<<<BB, 320>>>(f_lens, w_g, w_o, b_o, out, out_size);
}

// round 7
// speedup vs baseline: 1.1651x; 1.1651x over previous
#include <cuda_runtime.h>
#include <math.h>

#define TT 200
#define BB 128
#define FH 1024
#define PH 320
#define JH 512
#define VV 29
#define BLANKV 28
#define NSTEP 400
#define MAXL 256
#define YSN (NSTEP*BB*VV)

// ---------------- device scratch (no runtime allocation) ----------------
__device__ float  g_Fproj[(size_t)TT*BB*JH];   // f @ w_f + b_j
__device__ float4 g_xg0[VV*PH];                // embed@w_ih0+b0, [v][p][gate]
__device__ float4 g_wA [PH*PH];                // w_hh0 [k][p][gate]
__device__ float4 g_wB1[PH*PH];                // w_ih1 [k][p][gate]
__device__ float4 g_wB2[PH*PH];                // w_hh1 [k][p][gate]
__device__ float4 g_b1r[PH];                   // b1 [p][gate]

__device__ float g_h0[BB*PH], g_c0[BB*PH], g_h1[BB*PH], g_c1[BB*PH];
__device__ float g_h0n[BB*PH], g_c0n[BB*PH], g_h1n[BB*PH], g_c1n[BB*PH];
__device__ float g_jrelu[BB*JH];
__device__ int g_pre[BB], g_time[BB], g_olen[BB];
__device__ int g_tok[BB*MAXL];
__device__ unsigned g_eq[NSTEP];
__device__ unsigned g_gcnt[4], g_grel[4], g_bcnt, g_brel;

__device__ __forceinline__ float sigf(float x){ return 1.0f/(1.0f+expf(-x)); }

// monotonic-counter barrier over n CTAs (one arrival per CTA)
__device__ __forceinline__ void barwait(unsigned* cnt, unsigned* rel, unsigned n){
    __syncthreads();
    if (threadIdx.x == 0){
        __threadfence();
        unsigned a = atomicAdd(cnt, 1u) + 1u;
        if (a % n == 0u){
            atomicMax(rel, a);
        } else {
            unsigned tgt = ((a + n - 1u)/n)*n;
            while (*(volatile unsigned*)rel < tgt) __nanosleep(32);
        }
        __threadfence();
    }
    __syncthreads();
}

// ---------------- init ----------------
__global__ void init_kernel(){
    int i = blockIdx.x*256 + threadIdx.x;
    if (i < BB*PH){ g_h0[i]=0.f; g_c0[i]=0.f; g_h1[i]=0.f; g_c1[i]=0.f; }
    if (i < BB){ g_pre[i]=0; g_time[i]=0; g_olen[i]=0; }
    if (i < BB*MAXL) g_tok[i] = BLANKV;
    if (i < NSTEP) g_eq[i] = 0u;
    if (i < 4){ g_gcnt[i]=0u; g_grel[i]=0u; }
    if (i == 0){ g_bcnt=0u; g_brel=0u; }
}

// ---------------- weight re-layout [k][4*PH gate-major] -> [k][p][gate] ----------------
__global__ void rearr_kernel(const float* __restrict__ w_hh0, const float* __restrict__ w_ih1,
                             const float* __restrict__ w_hh1, const float* __restrict__ b1){
    int i = blockIdx.x*256 + threadIdx.x;
    const int Nt = PH*PH*4;
    if (i < Nt){
        int g = i & 3, p = (i >> 2) % PH, k = i / (PH*4);
        int src = k*(4*PH) + g*PH + p;
        ((float*)g_wA )[i] = w_hh0[src];
        ((float*)g_wB1)[i] = w_ih1[src];
        ((float*)g_wB2)[i] = w_hh1[src];
    }
    if (i < PH*4){
        int g = i & 3, p = i >> 2;
        ((float*)g_b1r)[i] = b1[g*PH + p];
    }
}

// ---------------- xg0[v][p][g] = b0 + embed[v,:] @ w_ih0[:,g*PH+p] ----------------
__global__ void xg0_kernel(const float* __restrict__ embed, const float* __restrict__ w_ih0,
                           const float* __restrict__ b0v){
    __shared__ float es[PH];
    int v = blockIdx.x;
    for (int k = threadIdx.x; k < PH; k += 256) es[k] = embed[v*PH + k];
    __syncthreads();
    for (int j = threadIdx.x; j < PH*4; j += 256){
        int p = j >> 2, g = j & 3;
        float a = b0v[g*PH + p];
        const float* w = w_ih0 + g*PH + p;
        for (int k = 0; k < PH; k++) a = fmaf(es[k], w[k*(4*PH)], a);
        ((float*)g_xg0)[v*PH*4 + j] = a;
    }
}

// ---------------- Fproj = f(25600x1024) @ w_f(1024x512) + b_j ----------------
__global__ void __launch_bounds__(256) fproj_kernel(const float* __restrict__ A,
                                                    const float* __restrict__ Bm,
                                                    const float* __restrict__ bj){
    const int N = JH, K = FH;
    __shared__ float As[64][17];
    __shared__ float Bs[16][68];
    int bm = blockIdx.y*64, bn = blockIdx.x*64;
    int tid = threadIdx.x;
    int tx = tid & 15, ty = tid >> 4;
    float acc[4][4];
#pragma unroll
    for (int i = 0; i < 4; i++)
#pragma unroll
        for (int j = 0; j < 4; j++) acc[i][j] = 0.f;

    int lm = tid >> 2, lkq = tid & 3;
    int lk = tid >> 4, lnq = tid & 15;
    for (int k0 = 0; k0 < K; k0 += 16){
        float4 va = *(const float4*)(A + (size_t)(bm+lm)*K + k0 + lkq*4);
        As[lm][lkq*4+0]=va.x; As[lm][lkq*4+1]=va.y; As[lm][lkq*4+2]=va.z; As[lm][lkq*4+3]=va.w;
        float4 vb = *(const float4*)(Bm + (size_t)(k0+lk)*N + bn + lnq*4);
        Bs[lk][lnq*4+0]=vb.x; Bs[lk][lnq*4+1]=vb.y; Bs[lk][lnq*4+2]=vb.z; Bs[lk][lnq*4+3]=vb.w;
        __syncthreads();
#pragma unroll
        for (int k = 0; k < 16; k++){
            float a0=As[ty*4+0][k], a1=As[ty*4+1][k], a2=As[ty*4+2][k], a3=As[ty*4+3][k];
            float b0=Bs[k][tx*4+0], b1=Bs[k][tx*4+1], b2=Bs[k][tx*4+2], b3=Bs[k][tx*4+3];
            acc[0][0]=fmaf(a0,b0,acc[0][0]); acc[0][1]=fmaf(a0,b1,acc[0][1]);
            acc[0][2]=fmaf(a0,b2,acc[0][2]); acc[0][3]=fmaf(a0,b3,acc[0][3]);
            acc[1][0]=fmaf(a1,b0,acc[1][0]); acc[1][1]=fmaf(a1,b1,acc[1][1]);
            acc[1][2]=fmaf(a1,b2,acc[1][2]); acc[1][3]=fmaf(a1,b3,acc[1][3]);
            acc[2][0]=fmaf(a2,b0,acc[2][0]); acc[2][1]=fmaf(a2,b1,acc[2][1]);
            acc[2][2]=fmaf(a2,b2,acc[2][2]); acc[2][3]=fmaf(a2,b3,acc[2][3]);
            acc[3][0]=fmaf(a3,b0,acc[3][0]); acc[3][1]=fmaf(a3,b1,acc[3][1]);
            acc[3][2]=fmaf(a3,b2,acc[3][2]); acc[3][3]=fmaf(a3,b3,acc[3][3]);
        }
        __syncthreads();
    }
#pragma unroll
    for (int i = 0; i < 4; i++)
#pragma unroll
        for (int j = 0; j < 4; j++){
            int n = bn + tx*4 + j;
            g_Fproj[(size_t)(bm + ty*4 + i)*N + n] = acc[i][j] + bj[n];
        }
}

// ================= persistent decode: 128 CTAs x 320 threads =================
// SMEM layout (dynamic, ~216.5 KB):
//   swA  [PH][10] float4  (51200 B)   w_hh0 slice (persistent)
//   swB1 [PH][10] float4  (51200 B)   w_ih1 slice (persistent)
//   swB2 [PH][10] float4  (51200 B)   w_hh1 slice (persistent)
//   swg  [PH][16] float   (20480 B)   w_g slice   (persistent)
//   smh  [PH][33] float   (42240 B)   h tile, reloaded each phase
//   smy  [32] float, smnb int
#define SW_F4   3200                    // float4 count per LSTM weight slice
#define SMH_F   (PH*33)

__global__ void __launch_bounds__(320,1)
decode_kernel(const int* __restrict__ f_lens, const float* __restrict__ w_g,
              const float* __restrict__ w_o, const float* __restrict__ b_o,
              float* __restrict__ out, int out_size){
    extern __shared__ float smem[];
    float4* swA  = (float4*)smem;
    float4* swB1 = swA  + SW_F4;
    float4* swB2 = swB1 + SW_F4;
    float*  swg  = (float*)(swB2 + SW_F4);
    float*  smh  = swg + PH*16;
    float*  smy  = smh + SMH_F;
    int*    smnb = (int*)(smy + 32);

    const int tid = threadIdx.x;
    const int cta = blockIdx.x;
    const int bb  = cta >> 5;           // batch block 0..3
    const int sub = cta & 31;           // p/j slice 0..31
    const int b0  = bb*32;
    const int bl  = tid & 31, pl = tid >> 5;   // batch lane, p-within-slice (warp id)
    const int myb = cta;
    const int lane = tid & 31, wrp = tid >> 5;

    // ---- one-time weight preload into SMEM ----
    for (int i = tid; i < SW_F4; i += 320){
        int k = i/10, q = i - k*10;
        int src = k*PH + sub*10 + q;
        swA [i] = g_wA [src];
        swB1[i] = g_wB1[src];
        swB2[i] = g_wB2[src];
    }
    for (int i = tid; i < PH*16; i += 320)
        swg[i] = w_g[(size_t)(i>>4)*JH + sub*16 + (i & 15)];
    __syncthreads();

    const ulonglong2* wA64  = (const ulonglong2*)swA;
    const ulonglong2* wB164 = (const ulonglong2*)swB1;
    const ulonglong2* wB264 = (const ulonglong2*)swB2;

    for (int step = 0; step < NSTEP; step++){
        // ============ phase A: LSTM0 ============
        for (int e = tid; e < 32*PH; e += 320){
            int bi = e/PH, k = e - bi*PH;
            smh[k*33 + bi] = __ldcg(&g_h0[(b0+bi)*PH + k]);
        }
        __syncthreads();
        {
            const int p = sub*10 + pl;
            const int bgl = b0 + bl;
            int pre = __ldcg(&g_pre[bgl]);
            float4 a0 = g_xg0[pre*PH + p];
            unsigned long long acc01, acc23;
            asm("mov.b64 %0,{%1,%2};" : "=l"(acc01) : "f"(a0.x), "f"(a0.y));
            asm("mov.b64 %0,{%1,%2};" : "=l"(acc23) : "f"(a0.z), "f"(a0.w));
#pragma unroll 4
            for (int k = 0; k < PH; k++){
                float h = smh[k*33 + bl];
                ulonglong2 w = wA64[k*10 + pl];
                unsigned long long hh;
                asm("mov.b64 %0,{%1,%1};" : "=l"(hh) : "f"(h));
                asm("fma.rn.f32x2 %0,%1,%2,%0;" : "+l"(acc01) : "l"(hh), "l"(w.x));
                asm("fma.rn.f32x2 %0,%1,%2,%0;" : "+l"(acc23) : "l"(hh), "l"(w.y));
            }
            float gi,gf,gg,go;
            asm("mov.b64 {%0,%1},%2;" : "=f"(gi), "=f"(gf) : "l"(acc01));
            asm("mov.b64 {%0,%1},%2;" : "=f"(gg), "=f"(go) : "l"(acc23));
            float c  = __ldcg(&g_c0[bgl*PH + p]);
            float cn = sigf(gf)*c + sigf(gi)*tanhf(gg);
            float hn = sigf(go)*tanhf(cn);
            __stcg(&g_c0n[bgl*PH + p], cn);
            __stcg(&g_h0n[bgl*PH + p], hn);
        }
        barwait(&g_gcnt[bb], &g_grel[bb], 32u);

        // ============ phase B: LSTM1 (K = 320 + 320) ============
        {
            const int p = sub*10 + pl;
            const int bgl = b0 + bl;
            float4 bv = g_b1r[p];
            unsigned long long acc01, acc23;
            asm("mov.b64 %0,{%1,%2};" : "=l"(acc01) : "f"(bv.x), "f"(bv.y));
            asm("mov.b64 %0,{%1,%2};" : "=l"(acc23) : "f"(bv.z), "f"(bv.w));
#pragma unroll 1
            for (int pass = 0; pass < 2; pass++){
                const float* hin = pass ? g_h1 : g_h0n;
                const ulonglong2* W = pass ? wB264 : wB164;
                for (int e = tid; e < 32*PH; e += 320){
                    int bi = e/PH, k = e - bi*PH;
                    smh[k*33 + bi] = __ldcg(&hin[(b0+bi)*PH + k]);
                }
                __syncthreads();
#pragma unroll 4
                for (int k = 0; k < PH; k++){
                    float h = smh[k*33 + bl];
                    ulonglong2 w = W[k*10 + pl];
                    unsigned long long hh;
                    asm("mov.b64 %0,{%1,%1};" : "=l"(hh) : "f"(h));
                    asm("fma.rn.f32x2 %0,%1,%2,%0;" : "+l"(acc01) : "l"(hh), "l"(w.x));
                    asm("fma.rn.f32x2 %0,%1,%2,%0;" : "+l"(acc23) : "l"(hh), "l"(w.y));
                }
                __syncthreads();
            }
            float gi,gf,gg,go;
            asm("mov.b64 {%0,%1},%2;" : "=f"(gi), "=f"(gf) : "l"(acc01));
            asm("mov.b64 {%0,%1},%2;" : "=f"(gg), "=f"(go) : "l"(acc23));
            float c  = __ldcg(&g_c1[bgl*PH + p]);
            float cn = sigf(gf)*c + sigf(gi)*tanhf(gg);
            float hn = sigf(go)*tanhf(cn);
            __stcg(&g_c1n[bgl*PH + p], cn);
            __stcg(&g_h1n[bgl*PH + p], hn);
        }
        barwait(&g_gcnt[bb], &g_grel[bb], 32u);

        // ============ phase C: jrelu = relu(Fproj[time[b]] + h1n @ w_g) ============
        {
            const int bgl = b0 + bl;
            for (int e = tid; e < 32*PH; e += 320){
                int bi = e/PH, k = e - bi*PH;
                smh[k*33 + bi] = __ldcg(&g_h1n[(b0+bi)*PH + k]);
            }
            __syncthreads();
            float acc1 = 0.f, acc2 = 0.f;
#pragma unroll 4
            for (int k = 0; k < PH; k++){
                float h = smh[k*33 + bl];
                acc1 = fmaf(h, swg[k*16 + pl], acc1);
                if (pl < 6) acc2 = fmaf(h, swg[k*16 + pl + 10], acc2);
            }
            int t = __ldcg(&g_time[bgl]);
            size_t fb = ((size_t)t*BB + bgl)*JH + sub*16;
            float r1 = g_Fproj[fb + pl] + acc1;
            __stcg(&g_jrelu[bgl*JH + sub*16 + pl], r1 > 0.f ? r1 : 0.f);
            if (pl < 6){
                float r2 = g_Fproj[fb + pl + 10] + acc2;
                __stcg(&g_jrelu[bgl*JH + sub*16 + pl + 10], r2 > 0.f ? r2 : 0.f);
            }
        }
        barwait(&g_gcnt[bb], &g_grel[bb], 32u);

        // ============ phase D: logits + argmax + commit (CTA = batch) ============
        {
            for (int e = tid; e < JH; e += 320)
                smh[e] = __ldcg(&g_jrelu[myb*JH + e]);
            __syncthreads();
#pragma unroll
            for (int vi = 0; vi < 3; vi++){
                int v = wrp + vi*10;
                if (v < VV){
                    float a = 0.f;
#pragma unroll
                    for (int k = lane; k < JH; k += 32)
                        a = fmaf(smh[k], w_o[(size_t)k*VV + v], a);
#pragma unroll
                    for (int off = 16; off > 0; off >>= 1)
                        a += __shfl_xor_sync(0xffffffffu, a, off);
                    if (lane == 0) smy[v] = a + b_o[v];
                }
            }
            __syncthreads();
            if (tid < VV){
                int idx = (step*BB + myb)*VV + tid;
                if (idx < out_size) out[idx] = smy[tid];
            }
            if (tid == 0){
                int sym = 0; float best = smy[0];
                for (int v = 1; v < VV; v++) if (smy[v] > best){ best = smy[v]; sym = v; }
                int fin = (step > 0) && (__ldcg(&g_eq[step-1]) == (unsigned)BB);
                int nb  = (!fin) && (sym != BLANKV);
                int blk = (!fin) && (sym == BLANKV);
                if (nb){
                    int olen = g_olen[myb];
                    int pos = olen < (MAXL-1) ? olen : (MAXL-1);
                    g_tok[myb*MAXL + pos] = sym;
                    g_olen[myb] = olen + 1;
                    __stcg(&g_pre[myb], sym);
                }
                int tm  = __ldcg(&g_time[myb]);
                int eos = f_lens[myb] - 1;
                if (blk){ tm = tm + 1; if (tm > eos) tm = eos; }
                __stcg(&g_time[myb], tm);
                if (tm == eos) atomicAdd(&g_eq[step], 1u);
                *smnb = nb;
            }
            __syncthreads();
            if (*smnb){
                int i = myb*PH + tid;
                __stcg(&g_h0[i], __ldcg(&g_h0n[i]));
                __stcg(&g_c0[i], __ldcg(&g_c0n[i]));
                __stcg(&g_h1[i], __ldcg(&g_h1n[i]));
                __stcg(&g_c1[i], __ldcg(&g_c1n[i]));
            }
        }
        barwait(&g_bcnt, &g_brel, 128u);
    }

    // final: tokens + out_lens (cast to float), CTA = batch
    if (tid < MAXL){
        int idx = YSN + myb*MAXL + tid;
        if (idx < out_size) out[idx] = (float)g_tok[myb*MAXL + tid];
    }
    if (tid == 0){
        int idx = YSN + BB*MAXL + myb;
        if (idx < out_size) out[idx] = (float)g_olen[myb];
    }
}

extern "C" void kernel_launch(void* const* d_in, const int* in_sizes, int n_in,
                              void* d_out, int out_size){
    const float* f      = (const float*)d_in[0];
    const int*   f_lens = (const int*)  d_in[1];
    const float* embed  = (const float*)d_in[2];
    const float* w_ih0  = (const float*)d_in[3];
    const float* w_hh0  = (const float*)d_in[4];
    const float* b0     = (const float*)d_in[5];
    const float* w_ih1  = (const float*)d_in[6];
    const float* w_hh1  = (const float*)d_in[7];
    const float* b1     = (const float*)d_in[8];
    const float* w_f    = (const float*)d_in[9];
    const float* w_g    = (const float*)d_in[10];
    const float* b_j    = (const float*)d_in[11];
    const float* w_o    = (const float*)d_in[12];
    const float* b_o    = (const float*)d_in[13];
    float* out = (float*)d_out;

    // 3*51200 (wA/wB1/wB2) + 20480 (wg) + 42240 (h) + 144 (y/nb pad)
    const int smem_bytes = 3*51200 + 20480 + 42240 + 256;
    cudaFuncSetAttribute(decode_kernel, cudaFuncAttributeMaxDynamicSharedMemorySize, smem_bytes);

    init_kernel<<<160, 256>>>();
    rearr_kernel<<<1600, 256>>>(w_hh0, w_ih1, w_hh1, b1);
    xg0_kernel<<<VV, 256>>>(embed, w_ih0, b0);
    fproj_kernel<<<dim3(JH/64, (TT*BB)/64), 256>>>(f, w_f, b_j);
    decode_kernel<<<BB, 320, smem_bytes>>>(f_lens, w_g, w_o, b_o, out, out_size);
}

// round 8
// speedup vs baseline: 1.4688x; 1.2607x over previous
#include <cuda_runtime.h>
#include <math.h>

#define TT 200
#define BB 128
#define FH 1024
#define PH 320
#define JH 512
#define VV 29
#define BLANKV 28
#define NSTEP 400
#define MAXL 256
#define YSN (NSTEP*BB*VV)

// ---------------- device scratch (no runtime allocation) ----------------
__device__ float  g_Fproj[(size_t)TT*BB*JH];   // f @ w_f + b_j
__device__ float4 g_xg0[VV*PH];                // embed@w_ih0+b0, [v][p][gate]
__device__ float4 g_wA [PH*PH];                // w_hh0 [k][p][gate]
__device__ float4 g_wB1[PH*PH];                // w_ih1 [k][p][gate]
__device__ float4 g_wB2[PH*PH];                // w_hh1 [k][p][gate]
__device__ float4 g_b1r[PH];                   // b1 [p][gate]
__device__ float  g_woT[VV*JH];                // w_o transposed [v][k]

__device__ float g_h0[BB*PH], g_c0[BB*PH], g_h1[BB*PH], g_c1[BB*PH];
__device__ float g_h0n[BB*PH], g_c0n[BB*PH], g_h1n[BB*PH], g_c1n[BB*PH];
__device__ float g_jrelu[BB*JH];
__device__ int g_pre[BB], g_time[BB], g_olen[BB];
__device__ int g_tok[BB*MAXL];
__device__ unsigned g_eq[NSTEP];
__device__ unsigned g_gcnt[4], g_grel[4], g_bcnt, g_brel;

__device__ __forceinline__ float sigf(float x){ return 1.0f/(1.0f+expf(-x)); }

// acq/rel monotonic barrier over n CTAs (no full fence, no L1 invalidation)
__device__ __forceinline__ void barwait(unsigned* cnt, unsigned* rel, unsigned n){
    __syncthreads();
    if (threadIdx.x == 0){
        unsigned a;
        asm volatile("atom.add.release.gpu.global.u32 %0,[%1],1;"
                     : "=r"(a) : "l"(cnt) : "memory");
        a += 1u;
        if (a % n == 0u){
            asm volatile("red.release.gpu.global.max.u32 [%0],%1;"
                         :: "l"(rel), "r"(a) : "memory");
        } else {
            unsigned tgt = ((a + n - 1u)/n)*n;
            unsigned v;
            do {
                asm volatile("ld.acquire.gpu.global.u32 %0,[%1];"
                             : "=r"(v) : "l"(rel) : "memory");
            } while (v < tgt);
        }
    }
    __syncthreads();
}

__device__ __forceinline__ unsigned long long dup2(float h){
    unsigned long long r;
    asm("mov.b64 %0,{%1,%1};" : "=l"(r) : "f"(h));
    return r;
}
__device__ __forceinline__ void fma2(unsigned long long& acc, unsigned long long a, unsigned long long b){
    asm("fma.rn.f32x2 %0,%1,%2,%0;" : "+l"(acc) : "l"(a), "l"(b));
}

// ---------------- init ----------------
__global__ void init_kernel(){
    int i = blockIdx.x*256 + threadIdx.x;
    if (i < BB*PH){ g_h0[i]=0.f; g_c0[i]=0.f; g_h1[i]=0.f; g_c1[i]=0.f; }
    if (i < BB){ g_pre[i]=0; g_time[i]=0; g_olen[i]=0; }
    if (i < BB*MAXL) g_tok[i] = BLANKV;
    if (i < NSTEP) g_eq[i] = 0u;
    if (i < 4){ g_gcnt[i]=0u; g_grel[i]=0u; }
    if (i == 0){ g_bcnt=0u; g_brel=0u; }
}

// ---------------- weight re-layouts ----------------
__global__ void rearr_kernel(const float* __restrict__ w_hh0, const float* __restrict__ w_ih1,
                             const float* __restrict__ w_hh1, const float* __restrict__ b1,
                             const float* __restrict__ w_o){
    int i = blockIdx.x*256 + threadIdx.x;
    const int Nt = PH*PH*4;
    if (i < Nt){
        int g = i & 3, p = (i >> 2) % PH, k = i / (PH*4);
        int src = k*(4*PH) + g*PH + p;
        ((float*)g_wA )[i] = w_hh0[src];
        ((float*)g_wB1)[i] = w_ih1[src];
        ((float*)g_wB2)[i] = w_hh1[src];
    }
    if (i < PH*4){
        int g = i & 3, p = i >> 2;
        ((float*)g_b1r)[i] = b1[g*PH + p];
    }
    if (i < VV*JH){
        int v = i / JH, k = i - v*JH;
        g_woT[i] = w_o[k*VV + v];
    }
}

// ---------------- xg0[v][p][g] = b0 + embed[v,:] @ w_ih0[:,g*PH+p] ----------------
__global__ void xg0_kernel(const float* __restrict__ embed, const float* __restrict__ w_ih0,
                           const float* __restrict__ b0v){
    __shared__ float es[PH];
    int v = blockIdx.x;
    for (int k = threadIdx.x; k < PH; k += 256) es[k] = embed[v*PH + k];
    __syncthreads();
    for (int j = threadIdx.x; j < PH*4; j += 256){
        int p = j >> 2, g = j & 3;
        float a = b0v[g*PH + p];
        const float* w = w_ih0 + g*PH + p;
        for (int k = 0; k < PH; k++) a = fmaf(es[k], w[k*(4*PH)], a);
        ((float*)g_xg0)[v*PH*4 + j] = a;
    }
}

// ---------------- Fproj = f(25600x1024) @ w_f(1024x512) + b_j ----------------
__global__ void __launch_bounds__(256) fproj_kernel(const float* __restrict__ A,
                                                    const float* __restrict__ Bm,
                                                    const float* __restrict__ bj){
    const int N = JH, K = FH;
    __shared__ float As[64][17];
    __shared__ float Bs[16][68];
    int bm = blockIdx.y*64, bn = blockIdx.x*64;
    int tid = threadIdx.x;
    int tx = tid & 15, ty = tid >> 4;
    float acc[4][4];
#pragma unroll
    for (int i = 0; i < 4; i++)
#pragma unroll
        for (int j = 0; j < 4; j++) acc[i][j] = 0.f;

    int lm = tid >> 2, lkq = tid & 3;
    int lk = tid >> 4, lnq = tid & 15;
    for (int k0 = 0; k0 < K; k0 += 16){
        float4 va = *(const float4*)(A + (size_t)(bm+lm)*K + k0 + lkq*4);
        As[lm][lkq*4+0]=va.x; As[lm][lkq*4+1]=va.y; As[lm][lkq*4+2]=va.z; As[lm][lkq*4+3]=va.w;
        float4 vb = *(const float4*)(Bm + (size_t)(k0+lk)*N + bn + lnq*4);
        Bs[lk][lnq*4+0]=vb.x; Bs[lk][lnq*4+1]=vb.y; Bs[lk][lnq*4+2]=vb.z; Bs[lk][lnq*4+3]=vb.w;
        __syncthreads();
#pragma unroll
        for (int k = 0; k < 16; k++){
            float a0=As[ty*4+0][k], a1=As[ty*4+1][k], a2=As[ty*4+2][k], a3=As[ty*4+3][k];
            float b0=Bs[k][tx*4+0], b1=Bs[k][tx*4+1], b2=Bs[k][tx*4+2], b3=Bs[k][tx*4+3];
            acc[0][0]=fmaf(a0,b0,acc[0][0]); acc[0][1]=fmaf(a0,b1,acc[0][1]);
            acc[0][2]=fmaf(a0,b2,acc[0][2]); acc[0][3]=fmaf(a0,b3,acc[0][3]);
            acc[1][0]=fmaf(a1,b0,acc[1][0]); acc[1][1]=fmaf(a1,b1,acc[1][1]);
            acc[1][2]=fmaf(a1,b2,acc[1][2]); acc[1][3]=fmaf(a1,b3,acc[1][3]);
            acc[2][0]=fmaf(a2,b0,acc[2][0]); acc[2][1]=fmaf(a2,b1,acc[2][1]);
            acc[2][2]=fmaf(a2,b2,acc[2][2]); acc[2][3]=fmaf(a2,b3,acc[2][3]);
            acc[3][0]=fmaf(a3,b0,acc[3][0]); acc[3][1]=fmaf(a3,b1,acc[3][1]);
            acc[3][2]=fmaf(a3,b2,acc[3][2]); acc[3][3]=fmaf(a3,b3,acc[3][3]);
        }
        __syncthreads();
    }
#pragma unroll
    for (int i = 0; i < 4; i++)
#pragma unroll
        for (int j = 0; j < 4; j++){
            int n = bn + tx*4 + j;
            g_Fproj[(size_t)(bm + ty*4 + i)*N + n] = acc[i][j] + bj[n];
        }
}

// ================= persistent decode: 128 CTAs x 320 threads =================
// SMEM: swA/swB1/swB2 (3x51200) + swg (20480) + smh [32 batches][324] (41472) + smy/smnb
#define SW_F4  3200
#define HSTR   324                     // stride %32==4 -> conflict-free LDS.128
#define SMH_F  (32*HSTR)

__global__ void __launch_bounds__(320,1)
decode_kernel(const int* __restrict__ f_lens, const float* __restrict__ w_g,
              const float* __restrict__ b_o,
              float* __restrict__ out, int out_size){
    extern __shared__ float smem[];
    float4* swA  = (float4*)smem;
    float4* swB1 = swA  + SW_F4;
    float4* swB2 = swB1 + SW_F4;
    float*  swg  = (float*)(swB2 + SW_F4);
    float*  smh  = swg + PH*16;
    float*  smy  = smh + SMH_F;
    int*    smnb = (int*)(smy + 32);

    const int tid = threadIdx.x;
    const int cta = blockIdx.x;
    const int bb  = cta >> 5;           // batch block 0..3
    const int sub = cta & 31;           // p/j slice 0..31
    const int b0  = bb*32;
    const int bl  = tid & 31, pl = tid >> 5;   // batch lane, warp id
    const int myb = cta;
    const int lane = tid & 31, wrp = tid >> 5;

    // ---- one-time weight preload ----
    for (int i = tid; i < SW_F4; i += 320){
        int k = i/10, q = i - k*10;
        int src = k*PH + sub*10 + q;
        swA [i] = g_wA [src];
        swB1[i] = g_wB1[src];
        swB2[i] = g_wB2[src];
    }
    for (int i = tid; i < PH*16; i += 320)
        swg[i] = w_g[(size_t)(i>>4)*JH + sub*16 + (i & 15)];
    __syncthreads();

    const ulonglong2* wA64  = (const ulonglong2*)swA;
    const ulonglong2* wB164 = (const ulonglong2*)swB1;
    const ulonglong2* wB264 = (const ulonglong2*)swB2;

    for (int step = 0; step < NSTEP; step++){
        // ============ phase A: LSTM0 ============
#pragma unroll 8
        for (int j = 0; j < 32; j++)
            smh[j*HSTR + tid] = __ldcg(&g_h0[(b0+j)*PH + tid]);
        __syncthreads();
        {
            const int p = sub*10 + pl;
            const int bgl = b0 + bl;
            int pre = __ldcg(&g_pre[bgl]);
            float4 a0 = g_xg0[pre*PH + p];
            unsigned long long acc01, acc23;
            asm("mov.b64 %0,{%1,%2};" : "=l"(acc01) : "f"(a0.x), "f"(a0.y));
            asm("mov.b64 %0,{%1,%2};" : "=l"(acc23) : "f"(a0.z), "f"(a0.w));
            const float4* hrow = (const float4*)(smh + bl*HSTR);
#pragma unroll 4
            for (int k4 = 0; k4 < PH/4; k4++){
                float4 h4 = hrow[k4];
                ulonglong2 w0 = wA64[(k4*4+0)*10 + pl];
                ulonglong2 w1 = wA64[(k4*4+1)*10 + pl];
                ulonglong2 w2 = wA64[(k4*4+2)*10 + pl];
                ulonglong2 w3 = wA64[(k4*4+3)*10 + pl];
                unsigned long long h;
                h = dup2(h4.x); fma2(acc01,h,w0.x); fma2(acc23,h,w0.y);
                h = dup2(h4.y); fma2(acc01,h,w1.x); fma2(acc23,h,w1.y);
                h = dup2(h4.z); fma2(acc01,h,w2.x); fma2(acc23,h,w2.y);
                h = dup2(h4.w); fma2(acc01,h,w3.x); fma2(acc23,h,w3.y);
            }
            float gi,gf,gg,go;
            asm("mov.b64 {%0,%1},%2;" : "=f"(gi), "=f"(gf) : "l"(acc01));
            asm("mov.b64 {%0,%1},%2;" : "=f"(gg), "=f"(go) : "l"(acc23));
            float c  = __ldcg(&g_c0[bgl*PH + p]);
            float cn = sigf(gf)*c + sigf(gi)*tanhf(gg);
            float hn = sigf(go)*tanhf(cn);
            __stcg(&g_c0n[bgl*PH + p], cn);
            __stcg(&g_h0n[bgl*PH + p], hn);
        }
        barwait(&g_gcnt[bb], &g_grel[bb], 32u);

        // ============ phase B: LSTM1 (K = 320 + 320) ============
        {
            const int p = sub*10 + pl;
            const int bgl = b0 + bl;
            float4 bv = g_b1r[p];
            unsigned long long acc01, acc23;
            asm("mov.b64 %0,{%1,%2};" : "=l"(acc01) : "f"(bv.x), "f"(bv.y));
            asm("mov.b64 %0,{%1,%2};" : "=l"(acc23) : "f"(bv.z), "f"(bv.w));
            const float4* hrow = (const float4*)(smh + bl*HSTR);
#pragma unroll 1
            for (int pass = 0; pass < 2; pass++){
                const float* hin = pass ? g_h1 : g_h0n;
                const ulonglong2* W = pass ? wB264 : wB164;
#pragma unroll 8
                for (int j = 0; j < 32; j++)
                    smh[j*HSTR + tid] = __ldcg(&hin[(b0+j)*PH + tid]);
                __syncthreads();
#pragma unroll 4
                for (int k4 = 0; k4 < PH/4; k4++){
                    float4 h4 = hrow[k4];
                    ulonglong2 w0 = W[(k4*4+0)*10 + pl];
                    ulonglong2 w1 = W[(k4*4+1)*10 + pl];
                    ulonglong2 w2 = W[(k4*4+2)*10 + pl];
                    ulonglong2 w3 = W[(k4*4+3)*10 + pl];
                    unsigned long long h;
                    h = dup2(h4.x); fma2(acc01,h,w0.x); fma2(acc23,h,w0.y);
                    h = dup2(h4.y); fma2(acc01,h,w1.x); fma2(acc23,h,w1.y);
                    h = dup2(h4.z); fma2(acc01,h,w2.x); fma2(acc23,h,w2.y);
                    h = dup2(h4.w); fma2(acc01,h,w3.x); fma2(acc23,h,w3.y);
                }
                __syncthreads();
            }
            float gi,gf,gg,go;
            asm("mov.b64 {%0,%1},%2;" : "=f"(gi), "=f"(gf) : "l"(acc01));
            asm("mov.b64 {%0,%1},%2;" : "=f"(gg), "=f"(go) : "l"(acc23));
            float c  = __ldcg(&g_c1[bgl*PH + p]);
            float cn = sigf(gf)*c + sigf(gi)*tanhf(gg);
            float hn = sigf(go)*tanhf(cn);
            __stcg(&g_c1n[bgl*PH + p], cn);
            __stcg(&g_h1n[bgl*PH + p], hn);
        }
        barwait(&g_gcnt[bb], &g_grel[bb], 32u);

        // ============ phase C: jrelu = relu(Fproj[time[b]] + h1n @ w_g) ============
        {
            const int bgl = b0 + bl;
#pragma unroll 8
            for (int j = 0; j < 32; j++)
                smh[j*HSTR + tid] = __ldcg(&g_h1n[(b0+j)*PH + tid]);
            __syncthreads();
            float acc1 = 0.f, acc2 = 0.f;
            const float4* hrow = (const float4*)(smh + bl*HSTR);
#pragma unroll 4
            for (int k4 = 0; k4 < PH/4; k4++){
                float4 h4 = hrow[k4];
                acc1 = fmaf(h4.x, swg[(k4*4+0)*16 + pl], acc1);
                acc1 = fmaf(h4.y, swg[(k4*4+1)*16 + pl], acc1);
                acc1 = fmaf(h4.z, swg[(k4*4+2)*16 + pl], acc1);
                acc1 = fmaf(h4.w, swg[(k4*4+3)*16 + pl], acc1);
                if (pl < 6){
                    acc2 = fmaf(h4.x, swg[(k4*4+0)*16 + pl + 10], acc2);
                    acc2 = fmaf(h4.y, swg[(k4*4+1)*16 + pl + 10], acc2);
                    acc2 = fmaf(h4.z, swg[(k4*4+2)*16 + pl + 10], acc2);
                    acc2 = fmaf(h4.w, swg[(k4*4+3)*16 + pl + 10], acc2);
                }
            }
            int t = __ldcg(&g_time[bgl]);
            size_t fb = ((size_t)t*BB + bgl)*JH + sub*16;
            float r1 = __ldcg(&g_Fproj[fb + pl]) + acc1;
            __stcg(&g_jrelu[bgl*JH + sub*16 + pl], r1 > 0.f ? r1 : 0.f);
            if (pl < 6){
                float r2 = __ldcg(&g_Fproj[fb + pl + 10]) + acc2;
                __stcg(&g_jrelu[bgl*JH + sub*16 + pl + 10], r2 > 0.f ? r2 : 0.f);
            }
        }
        barwait(&g_gcnt[bb], &g_grel[bb], 32u);

        // ============ phase D: logits + argmax + commit (CTA = batch) ============
        {
            __syncthreads();
            for (int e = tid; e < JH; e += 320)
                smh[e] = __ldcg(&g_jrelu[myb*JH + e]);
            __syncthreads();
#pragma unroll
            for (int vi = 0; vi < 3; vi++){
                int v = wrp + vi*10;
                if (v < VV){
                    float a = 0.f;
#pragma unroll
                    for (int k = lane; k < JH; k += 32)
                        a = fmaf(smh[k], __ldcg(&g_woT[v*JH + k]), a);
#pragma unroll
                    for (int off = 16; off > 0; off >>= 1)
                        a += __shfl_xor_sync(0xffffffffu, a, off);
                    if (lane == 0) smy[v] = a + b_o[v];
                }
            }
            __syncthreads();
            if (tid < VV){
                int idx = (step*BB + myb)*VV + tid;
                if (idx < out_size) out[idx] = smy[tid];
            }
            if (tid == 0){
                int sym = 0; float best = smy[0];
                for (int v = 1; v < VV; v++) if (smy[v] > best){ best = smy[v]; sym = v; }
                int fin = (step > 0) && (__ldcg(&g_eq[step-1]) == (unsigned)BB);
                int nb  = (!fin) && (sym != BLANKV);
                int blk = (!fin) && (sym == BLANKV);
                if (nb){
                    int olen = g_olen[myb];
                    int pos = olen < (MAXL-1) ? olen : (MAXL-1);
                    g_tok[myb*MAXL + pos] = sym;
                    g_olen[myb] = olen + 1;
                    __stcg(&g_pre[myb], sym);
                }
                int tm  = __ldcg(&g_time[myb]);
                int eos = f_lens[myb] - 1;
                if (blk){ tm = tm + 1; if (tm > eos) tm = eos; }
                __stcg(&g_time[myb], tm);
                if (tm == eos) atomicAdd(&g_eq[step], 1u);
                *smnb = nb;
            }
            __syncthreads();
            if (*smnb){
                int i = myb*PH + tid;
                __stcg(&g_h0[i], __ldcg(&g_h0n[i]));
                __stcg(&g_c0[i], __ldcg(&g_c0n[i]));
                __stcg(&g_h1[i], __ldcg(&g_h1n[i]));
                __stcg(&g_c1[i], __ldcg(&g_c1n[i]));
            }
        }
        barwait(&g_bcnt, &g_brel, 128u);
    }

    // final: tokens + out_lens (cast to float), CTA = batch
    if (tid < MAXL){
        int idx = YSN + myb*MAXL + tid;
        if (idx < out_size) out[idx] = (float)g_tok[myb*MAXL + tid];
    }
    if (tid == 0){
        int idx = YSN + BB*MAXL + myb;
        if (idx < out_size) out[idx] = (float)g_olen[myb];
    }
}

extern "C" void kernel_launch(void* const* d_in, const int* in_sizes, int n_in,
                              void* d_out, int out_size){
    const float* f      = (const float*)d_in[0];
    const int*   f_lens = (const int*)  d_in[1];
    const float* embed  = (const float*)d_in[2];
    const float* w_ih0  = (const float*)d_in[3];
    const float* w_hh0  = (const float*)d_in[4];
    const float* b0     = (const float*)d_in[5];
    const float* w_ih1  = (const float*)d_in[6];
    const float* w_hh1  = (const float*)d_in[7];
    const float* b1     = (const float*)d_in[8];
    const float* w_f    = (const float*)d_in[9];
    const float* w_g    = (const float*)d_in[10];
    const float* b_j    = (const float*)d_in[11];
    const float* w_o    = (const float*)d_in[12];
    const float* b_o    = (const float*)d_in[13];
    float* out = (float*)d_out;

    // 3*51200 + 20480 + 32*324*4 + 256 = 217,312 B
    const int smem_bytes = 3*51200 + 20480 + SMH_F*4 + 256;
    cudaFuncSetAttribute(decode_kernel, cudaFuncAttributeMaxDynamicSharedMemorySize, smem_bytes);

    init_kernel<<<160, 256>>>();
    rearr_kernel<<<1600, 256>>>(w_hh0, w_ih1, w_hh1, b1, w_o);
    xg0_kernel<<<VV, 256>>>(embed, w_ih0, b0);
    fproj_kernel<<<dim3(JH/64, (TT*BB)/64), 256>>>(f, w_f, b_j);
    decode_kernel<<<BB, 320, smem_bytes>>>(f_lens, w_g, b_o, out, out_size);
}

// round 9
// speedup vs baseline: 1.5420x; 1.0498x over previous
#include <cuda_runtime.h>
#include <math.h>

#define TT 200
#define BB 128
#define FH 1024
#define PH 320
#define JH 512
#define VV 29
#define BLANKV 28
#define NSTEP 400
#define MAXL 256
#define YSN (NSTEP*BB*VV)

// ---------------- device scratch (no runtime allocation) ----------------
__device__ float  g_Fproj[(size_t)TT*BB*JH];   // f @ w_f + b_j
__device__ float4 g_xg0[VV*PH];                // embed@w_ih0+b0, [v][p][gate]
__device__ float4 g_wA [PH*PH];                // w_hh0 [k][p][gate]
__device__ float4 g_wB1[PH*PH];                // w_ih1 [k][p][gate]
__device__ float4 g_wB2[PH*PH];                // w_hh1 [k][p][gate]
__device__ float4 g_b1r[PH];                   // b1 [p][gate]
__device__ float  g_woT[VV*JH];                // w_o transposed [v][k]

__device__ float g_h0[BB*PH], g_c0[BB*PH], g_h1[BB*PH], g_c1[BB*PH];
__device__ float g_h0n[BB*PH], g_c0n[BB*PH], g_h1n[BB*PH], g_c1n[BB*PH];
__device__ float g_jrelu[BB*JH];
__device__ int g_pre[BB], g_time[BB], g_olen[BB];
__device__ int g_tok[BB*MAXL];
__device__ unsigned g_eq[NSTEP];               // #batches at eos, per step
__device__ unsigned g_done[NSTEP];             // #CTAs finished phase D, per step
__device__ unsigned g_gcnt[4], g_grel[4];

__device__ __forceinline__ float sigf(float x){ return 1.0f/(1.0f+expf(-x)); }

// acq/rel monotonic barrier over n CTAs (group-local)
__device__ __forceinline__ void barwait(unsigned* cnt, unsigned* rel, unsigned n){
    __syncthreads();
    if (threadIdx.x == 0){
        unsigned a;
        asm volatile("atom.add.release.gpu.global.u32 %0,[%1],1;"
                     : "=r"(a) : "l"(cnt) : "memory");
        a += 1u;
        if (a % n == 0u){
            asm volatile("red.release.gpu.global.max.u32 [%0],%1;"
                         :: "l"(rel), "r"(a) : "memory");
        } else {
            unsigned tgt = ((a + n - 1u)/n)*n;
            unsigned v;
            do {
                asm volatile("ld.acquire.gpu.global.u32 %0,[%1];"
                             : "=r"(v) : "l"(rel) : "memory");
            } while (v < tgt);
        }
    }
    __syncthreads();
}

__device__ __forceinline__ unsigned long long dup2(float h){
    unsigned long long r;
    asm("mov.b64 %0,{%1,%1};" : "=l"(r) : "f"(h));
    return r;
}
__device__ __forceinline__ void fma2(unsigned long long& acc, unsigned long long a, unsigned long long b){
    asm("fma.rn.f32x2 %0,%1,%2,%0;" : "+l"(acc) : "l"(a), "l"(b));
}

// ---------------- init ----------------
__global__ void init_kernel(){
    int i = blockIdx.x*256 + threadIdx.x;
    if (i < BB*PH){ g_h0[i]=0.f; g_c0[i]=0.f; g_h1[i]=0.f; g_c1[i]=0.f; }
    if (i < BB){ g_pre[i]=0; g_time[i]=0; g_olen[i]=0; }
    if (i < BB*MAXL) g_tok[i] = BLANKV;
    if (i < NSTEP){ g_eq[i] = 0u; g_done[i] = 0u; }
    if (i < 4){ g_gcnt[i]=0u; g_grel[i]=0u; }
}

// ---------------- weight re-layouts ----------------
__global__ void rearr_kernel(const float* __restrict__ w_hh0, const float* __restrict__ w_ih1,
                             const float* __restrict__ w_hh1, const float* __restrict__ b1,
                             const float* __restrict__ w_o){
    int i = blockIdx.x*256 + threadIdx.x;
    const int Nt = PH*PH*4;
    if (i < Nt){
        int g = i & 3, p = (i >> 2) % PH, k = i / (PH*4);
        int src = k*(4*PH) + g*PH + p;
        ((float*)g_wA )[i] = w_hh0[src];
        ((float*)g_wB1)[i] = w_ih1[src];
        ((float*)g_wB2)[i] = w_hh1[src];
    }
    if (i < PH*4){
        int g = i & 3, p = i >> 2;
        ((float*)g_b1r)[i] = b1[g*PH + p];
    }
    if (i < VV*JH){
        int v = i / JH, k = i - v*JH;
        g_woT[i] = w_o[k*VV + v];
    }
}

// ---------------- xg0[v][p][g] = b0 + embed[v,:] @ w_ih0[:,g*PH+p] ----------------
__global__ void xg0_kernel(const float* __restrict__ embed, const float* __restrict__ w_ih0,
                           const float* __restrict__ b0v){
    __shared__ float es[PH];
    int v = blockIdx.x;
    for (int k = threadIdx.x; k < PH; k += 256) es[k] = embed[v*PH + k];
    __syncthreads();
    for (int j = threadIdx.x; j < PH*4; j += 256){
        int p = j >> 2, g = j & 3;
        float a = b0v[g*PH + p];
        const float* w = w_ih0 + g*PH + p;
        for (int k = 0; k < PH; k++) a = fmaf(es[k], w[k*(4*PH)], a);
        ((float*)g_xg0)[v*PH*4 + j] = a;
    }
}

// ---------------- Fproj: double-buffered, transposed-A tiles ----------------
__global__ void __launch_bounds__(256) fproj_kernel(const float* __restrict__ A,
                                                    const float* __restrict__ Bm,
                                                    const float* __restrict__ bj){
    const int N = JH, K = FH;
    __shared__ float Ast[2][16][68];   // [k][m], 68-pad keeps float4 reads 16B-aligned
    __shared__ float Bs [2][16][68];
    int bm = blockIdx.y*64, bn = blockIdx.x*64;
    int tid = threadIdx.x;
    int tx = tid & 15, ty = tid >> 4;
    int lm = tid >> 2, lkq = tid & 3;     // A loader: row lm, k-quad lkq
    int lk = tid >> 4, lnq = tid & 15;    // B loader: k lk, n-quad lnq

    float acc[4][4];
#pragma unroll
    for (int i = 0; i < 4; i++)
#pragma unroll
        for (int j = 0; j < 4; j++) acc[i][j] = 0.f;

    // prologue: tile 0
    float4 va = *(const float4*)(A + (size_t)(bm+lm)*K + lkq*4);
    float4 vb = *(const float4*)(Bm + (size_t)lk*N + bn + lnq*4);
    Ast[0][lkq*4+0][lm]=va.x; Ast[0][lkq*4+1][lm]=va.y;
    Ast[0][lkq*4+2][lm]=va.z; Ast[0][lkq*4+3][lm]=va.w;
    *(float4*)&Bs[0][lk][lnq*4] = vb;
    __syncthreads();

    int buf = 0;
    for (int k0 = 16; k0 < K; k0 += 16){
        va = *(const float4*)(A + (size_t)(bm+lm)*K + k0 + lkq*4);
        vb = *(const float4*)(Bm + (size_t)(k0+lk)*N + bn + lnq*4);
#pragma unroll
        for (int k = 0; k < 16; k++){
            float4 av = *(const float4*)&Ast[buf][k][ty*4];
            float4 bv = *(const float4*)&Bs [buf][k][tx*4];
            acc[0][0]=fmaf(av.x,bv.x,acc[0][0]); acc[0][1]=fmaf(av.x,bv.y,acc[0][1]);
            acc[0][2]=fmaf(av.x,bv.z,acc[0][2]); acc[0][3]=fmaf(av.x,bv.w,acc[0][3]);
            acc[1][0]=fmaf(av.y,bv.x,acc[1][0]); acc[1][1]=fmaf(av.y,bv.y,acc[1][1]);
            acc[1][2]=fmaf(av.y,bv.z,acc[1][2]); acc[1][3]=fmaf(av.y,bv.w,acc[1][3]);
            acc[2][0]=fmaf(av.z,bv.x,acc[2][0]); acc[2][1]=fmaf(av.z,bv.y,acc[2][1]);
            acc[2][2]=fmaf(av.z,bv.z,acc[2][2]); acc[2][3]=fmaf(av.z,bv.w,acc[2][3]);
            acc[3][0]=fmaf(av.w,bv.x,acc[3][0]); acc[3][1]=fmaf(av.w,bv.y,acc[3][1]);
            acc[3][2]=fmaf(av.w,bv.z,acc[3][2]); acc[3][3]=fmaf(av.w,bv.w,acc[3][3]);
        }
        int nb = buf ^ 1;
        Ast[nb][lkq*4+0][lm]=va.x; Ast[nb][lkq*4+1][lm]=va.y;
        Ast[nb][lkq*4+2][lm]=va.z; Ast[nb][lkq*4+3][lm]=va.w;
        *(float4*)&Bs[nb][lk][lnq*4] = vb;
        __syncthreads();
        buf = nb;
    }
#pragma unroll
    for (int k = 0; k < 16; k++){
        float4 av = *(const float4*)&Ast[buf][k][ty*4];
        float4 bv = *(const float4*)&Bs [buf][k][tx*4];
        acc[0][0]=fmaf(av.x,bv.x,acc[0][0]); acc[0][1]=fmaf(av.x,bv.y,acc[0][1]);
        acc[0][2]=fmaf(av.x,bv.z,acc[0][2]); acc[0][3]=fmaf(av.x,bv.w,acc[0][3]);
        acc[1][0]=fmaf(av.y,bv.x,acc[1][0]); acc[1][1]=fmaf(av.y,bv.y,acc[1][1]);
        acc[1][2]=fmaf(av.y,bv.z,acc[1][2]); acc[1][3]=fmaf(av.y,bv.w,acc[1][3]);
        acc[2][0]=fmaf(av.z,bv.x,acc[2][0]); acc[2][1]=fmaf(av.z,bv.y,acc[2][1]);
        acc[2][2]=fmaf(av.z,bv.z,acc[2][2]); acc[2][3]=fmaf(av.z,bv.w,acc[2][3]);
        acc[3][0]=fmaf(av.w,bv.x,acc[3][0]); acc[3][1]=fmaf(av.w,bv.y,acc[3][1]);
        acc[3][2]=fmaf(av.w,bv.z,acc[3][2]); acc[3][3]=fmaf(av.w,bv.w,acc[3][3]);
    }
#pragma unroll
    for (int i = 0; i < 4; i++)
#pragma unroll
        for (int j = 0; j < 4; j++){
            int n = bn + tx*4 + j;
            g_Fproj[(size_t)(bm + ty*4 + i)*N + n] = acc[i][j] + bj[n];
        }
}

// ================= persistent decode: 128 CTAs x 320 threads =================
#define SW_F4  3200
#define HSTR   324                     // %32==4 -> conflict-free LDS.128
#define SMH_F  (32*HSTR)

__global__ void __launch_bounds__(320,1)
decode_kernel(const int* __restrict__ f_lens, const float* __restrict__ w_g,
              const float* __restrict__ b_o,
              float* __restrict__ out, int out_size){
    extern __shared__ float smem[];
    float4* swA  = (float4*)smem;
    float4* swB1 = swA  + SW_F4;
    float4* swB2 = swB1 + SW_F4;
    float*  swg  = (float*)(swB2 + SW_F4);
    float*  smh  = swg + PH*16;
    float*  smy  = smh + SMH_F;
    int*    smnb = (int*)(smy + 32);

    const int tid = threadIdx.x;
    const int cta = blockIdx.x;
    const int bb  = cta >> 5;           // batch group 0..3
    const int sub = cta & 31;           // p/j slice 0..31
    const int b0  = bb*32;
    const int lane = tid & 31, wrp = tid >> 5;
    // remapped LSTM coords: warp = bhalf*5 + pduo; lane = 2*bl4 + psel
    const int psel = lane & 1, bl4 = lane >> 1;
    const int bhalf = (wrp < 5) ? 0 : 1, pduo = (wrp < 5) ? wrp : wrp - 5;
    const int bat = bhalf*16 + bl4;                // 0..31
    const int lp  = pduo*2 + psel;                 // 0..9
    const int p   = sub*10 + lp;
    const int bgl = b0 + bat;
    // phase-C coords (old mapping)
    const int blc = lane, plc = wrp;
    const int bglc = b0 + blc;
    const int myb = cta;

    // ---- one-time weight preload ----
    for (int i = tid; i < SW_F4; i += 320){
        int k = i/10, q = i - k*10;
        int src = k*PH + sub*10 + q;
        swA [i] = g_wA [src];
        swB1[i] = g_wB1[src];
        swB2[i] = g_wB2[src];
    }
    for (int i = tid; i < PH*16; i += 320)
        swg[i] = w_g[(size_t)(i>>4)*JH + sub*16 + (i & 15)];
    __syncthreads();

    const ulonglong2* wA64  = (const ulonglong2*)swA;
    const ulonglong2* wB164 = (const ulonglong2*)swB1;
    const ulonglong2* wB264 = (const ulonglong2*)swB2;
    const float4* hrow  = (const float4*)(smh + bat*HSTR);
    const float4* hrowc = (const float4*)(smh + blc*HSTR);

    for (int step = 0; step < NSTEP; step++){
        // ============ phase A: LSTM0 ============
#pragma unroll 8
        for (int j = 0; j < 32; j++)
            smh[j*HSTR + tid] = __ldcg(&g_h0[(b0+j)*PH + tid]);
        __syncthreads();
        {
            int pre = __ldcg(&g_pre[bgl]);
            float4 a0 = g_xg0[pre*PH + p];
            unsigned long long acc01, acc23;
            asm("mov.b64 %0,{%1,%2};" : "=l"(acc01) : "f"(a0.x), "f"(a0.y));
            asm("mov.b64 %0,{%1,%2};" : "=l"(acc23) : "f"(a0.z), "f"(a0.w));
#pragma unroll 4
            for (int k4 = 0; k4 < PH/4; k4++){
                float4 h4 = hrow[k4];
                ulonglong2 w0 = wA64[(k4*4+0)*10 + lp];
                ulonglong2 w1 = wA64[(k4*4+1)*10 + lp];
                ulonglong2 w2 = wA64[(k4*4+2)*10 + lp];
                ulonglong2 w3 = wA64[(k4*4+3)*10 + lp];
                unsigned long long h;
                h = dup2(h4.x); fma2(acc01,h,w0.x); fma2(acc23,h,w0.y);
                h = dup2(h4.y); fma2(acc01,h,w1.x); fma2(acc23,h,w1.y);
                h = dup2(h4.z); fma2(acc01,h,w2.x); fma2(acc23,h,w2.y);
                h = dup2(h4.w); fma2(acc01,h,w3.x); fma2(acc23,h,w3.y);
            }
            float gi,gf,gg,go;
            asm("mov.b64 {%0,%1},%2;" : "=f"(gi), "=f"(gf) : "l"(acc01));
            asm("mov.b64 {%0,%1},%2;" : "=f"(gg), "=f"(go) : "l"(acc23));
            float c  = __ldcg(&g_c0[bgl*PH + p]);
            float cn = sigf(gf)*c + sigf(gi)*tanhf(gg);
            float hn = sigf(go)*tanhf(cn);
            __stcg(&g_c0n[bgl*PH + p], cn);
            __stcg(&g_h0n[bgl*PH + p], hn);
        }
        barwait(&g_gcnt[bb], &g_grel[bb], 32u);

        // ============ phase B: LSTM1 (K = 320 + 320) ============
        {
            float4 bv = g_b1r[p];
            unsigned long long acc01, acc23;
            asm("mov.b64 %0,{%1,%2};" : "=l"(acc01) : "f"(bv.x), "f"(bv.y));
            asm("mov.b64 %0,{%1,%2};" : "=l"(acc23) : "f"(bv.z), "f"(bv.w));
#pragma unroll 1
            for (int pass = 0; pass < 2; pass++){
                const float* hin = pass ? g_h1 : g_h0n;
                const ulonglong2* W = pass ? wB264 : wB164;
#pragma unroll 8
                for (int j = 0; j < 32; j++)
                    smh[j*HSTR + tid] = __ldcg(&hin[(b0+j)*PH + tid]);
                __syncthreads();
#pragma unroll 4
                for (int k4 = 0; k4 < PH/4; k4++){
                    float4 h4 = hrow[k4];
                    ulonglong2 w0 = W[(k4*4+0)*10 + lp];
                    ulonglong2 w1 = W[(k4*4+1)*10 + lp];
                    ulonglong2 w2 = W[(k4*4+2)*10 + lp];
                    ulonglong2 w3 = W[(k4*4+3)*10 + lp];
                    unsigned long long h;
                    h = dup2(h4.x); fma2(acc01,h,w0.x); fma2(acc23,h,w0.y);
                    h = dup2(h4.y); fma2(acc01,h,w1.x); fma2(acc23,h,w1.y);
                    h = dup2(h4.z); fma2(acc01,h,w2.x); fma2(acc23,h,w2.y);
                    h = dup2(h4.w); fma2(acc01,h,w3.x); fma2(acc23,h,w3.y);
                }
                __syncthreads();
            }
            float gi,gf,gg,go;
            asm("mov.b64 {%0,%1},%2;" : "=f"(gi), "=f"(gf) : "l"(acc01));
            asm("mov.b64 {%0,%1},%2;" : "=f"(gg), "=f"(go) : "l"(acc23));
            float c  = __ldcg(&g_c1[bgl*PH + p]);
            float cn = sigf(gf)*c + sigf(gi)*tanhf(gg);
            float hn = sigf(go)*tanhf(cn);
            __stcg(&g_c1n[bgl*PH + p], cn);
            __stcg(&g_h1n[bgl*PH + p], hn);
        }
        barwait(&g_gcnt[bb], &g_grel[bb], 32u);

        // ============ phase C: jrelu = relu(Fproj[time[b]] + h1n @ w_g) ============
        {
#pragma unroll 8
            for (int j = 0; j < 32; j++)
                smh[j*HSTR + tid] = __ldcg(&g_h1n[(b0+j)*PH + tid]);
            __syncthreads();
            float acc1 = 0.f, acc2 = 0.f;
#pragma unroll 4
            for (int k4 = 0; k4 < PH/4; k4++){
                float4 h4 = hrowc[k4];
                acc1 = fmaf(h4.x, swg[(k4*4+0)*16 + plc], acc1);
                acc1 = fmaf(h4.y, swg[(k4*4+1)*16 + plc], acc1);
                acc1 = fmaf(h4.z, swg[(k4*4+2)*16 + plc], acc1);
                acc1 = fmaf(h4.w, swg[(k4*4+3)*16 + plc], acc1);
                if (plc < 6){
                    acc2 = fmaf(h4.x, swg[(k4*4+0)*16 + plc + 10], acc2);
                    acc2 = fmaf(h4.y, swg[(k4*4+1)*16 + plc + 10], acc2);
                    acc2 = fmaf(h4.z, swg[(k4*4+2)*16 + plc + 10], acc2);
                    acc2 = fmaf(h4.w, swg[(k4*4+3)*16 + plc + 10], acc2);
                }
            }
            int t = __ldcg(&g_time[bglc]);
            size_t fb = ((size_t)t*BB + bglc)*JH + sub*16;
            float r1 = __ldcg(&g_Fproj[fb + plc]) + acc1;
            __stcg(&g_jrelu[bglc*JH + sub*16 + plc], r1 > 0.f ? r1 : 0.f);
            if (plc < 6){
                float r2 = __ldcg(&g_Fproj[fb + plc + 10]) + acc2;
                __stcg(&g_jrelu[bglc*JH + sub*16 + plc + 10], r2 > 0.f ? r2 : 0.f);
            }
        }
        barwait(&g_gcnt[bb], &g_grel[bb], 32u);

        // ============ phase D: logits + argmax + commit (CTA = batch) ============
        {
            __syncthreads();
            for (int e = tid; e < JH; e += 320)
                smh[e] = __ldcg(&g_jrelu[myb*JH + e]);
            __syncthreads();
#pragma unroll
            for (int vi = 0; vi < 3; vi++){
                int v = wrp + vi*10;
                if (v < VV){
                    float a = 0.f;
#pragma unroll
                    for (int k = lane; k < JH; k += 32)
                        a = fmaf(smh[k], __ldcg(&g_woT[v*JH + k]), a);
#pragma unroll
                    for (int off = 16; off > 0; off >>= 1)
                        a += __shfl_xor_sync(0xffffffffu, a, off);
                    if (lane == 0) smy[v] = a + b_o[v];
                }
            }
            __syncthreads();
            if (tid < VV){
                int idx = (step*BB + myb)*VV + tid;
                if (idx < out_size) out[idx] = smy[tid];
            }
            if (tid == 0){
                int sym = 0; float best = smy[0];
                for (int v = 1; v < VV; v++) if (smy[v] > best){ best = smy[v]; sym = v; }
                int fin = 0;
                if (step > 0){
                    unsigned d;
                    do {
                        asm volatile("ld.acquire.gpu.global.u32 %0,[%1];"
                                     : "=r"(d) : "l"(&g_done[step-1]) : "memory");
                    } while (d < (unsigned)BB);
                    fin = (__ldcg(&g_eq[step-1]) == (unsigned)BB);
                }
                int nb  = (!fin) && (sym != BLANKV);
                int blk = (!fin) && (sym == BLANKV);
                if (nb){
                    int olen = g_olen[myb];
                    int pos = olen < (MAXL-1) ? olen : (MAXL-1);
                    g_tok[myb*MAXL + pos] = sym;
                    g_olen[myb] = olen + 1;
                    __stcg(&g_pre[myb], sym);
                }
                int tm  = __ldcg(&g_time[myb]);
                int eos = f_lens[myb] - 1;
                if (blk){ tm = tm + 1; if (tm > eos) tm = eos; }
                __stcg(&g_time[myb], tm);
                if (tm == eos) atomicAdd(&g_eq[step], 1u);
                unsigned du;
                asm volatile("atom.add.release.gpu.global.u32 %0,[%1],1;"
                             : "=r"(du) : "l"(&g_done[step]) : "memory");
                *smnb = nb;
            }
            __syncthreads();
            if (*smnb){
                int i = myb*PH + tid;
                __stcg(&g_h0[i], __ldcg(&g_h0n[i]));
                __stcg(&g_c0[i], __ldcg(&g_c0n[i]));
                __stcg(&g_h1[i], __ldcg(&g_h1n[i]));
                __stcg(&g_c1[i], __ldcg(&g_c1n[i]));
            }
        }
        barwait(&g_gcnt[bb], &g_grel[bb], 32u);   // group-local step boundary
    }

    // final: tokens + out_lens (cast to float), CTA = batch
    if (tid < MAXL){
        int idx = YSN + myb*MAXL + tid;
        if (idx < out_size) out[idx] = (float)g_tok[myb*MAXL + tid];
    }
    if (tid == 0){
        int idx = YSN + BB*MAXL + myb;
        if (idx < out_size) out[idx] = (float)g_olen[myb];
    }
}

extern "C" void kernel_launch(void* const* d_in, const int* in_sizes, int n_in,
                              void* d_out, int out_size){
    const float* f      = (const float*)d_in[0];
    const int*   f_lens = (const int*)  d_in[1];
    const float* embed  = (const float*)d_in[2];
    const float* w_ih0  = (const float*)d_in[3];
    const float* w_hh0  = (const float*)d_in[4];
    const float* b0     = (const float*)d_in[5];
    const float* w_ih1  = (const float*)d_in[6];
    const float* w_hh1  = (const float*)d_in[7];
    const float* b1     = (const float*)d_in[8];
    const float* w_f    = (const float*)d_in[9];
    const float* w_g    = (const float*)d_in[10];
    const float* b_j    = (const float*)d_in[11];
    const float* w_o    = (const float*)d_in[12];
    const float* b_o    = (const float*)d_in[13];
    float* out = (float*)d_out;

    const int smem_bytes = 3*51200 + 20480 + SMH_F*4 + 256;
    cudaFuncSetAttribute(decode_kernel, cudaFuncAttributeMaxDynamicSharedMemorySize, smem_bytes);

    init_kernel<<<160, 256>>>();
    rearr_kernel<<<1600, 256>>>(w_hh0, w_ih1, w_hh1, b1, w_o);
    xg0_kernel<<<VV, 256>>>(embed, w_ih0, b0);
    fproj_kernel<<<dim3(JH/64, (TT*BB)/64), 256>>>(f, w_f, b_j);
    decode_kernel<<<BB, 320, smem_bytes>>>(f_lens, w_g, b_o, out, out_size);
}

// round 10
// speedup vs baseline: 1.6454x; 1.0671x over previous
#include <cuda_runtime.h>
#include <math.h>

#define TT 200
#define BB 128
#define FH 1024
#define PH 320
#define JH 512
#define VV 29
#define BLANKV 28
#define NSTEP 400
#define MAXL 256
#define YSN (NSTEP*BB*VV)

// ---------------- device scratch (no runtime allocation) ----------------
__device__ float  g_Fproj[(size_t)TT*BB*JH];   // f @ w_f + b_j
__device__ float4 g_xg0[VV*PH];                // embed@w_ih0+b0, [v][p][gate]
__device__ float4 g_wA [PH*PH];                // w_hh0 [k][p][gate]
__device__ float4 g_wB1[PH*PH];                // w_ih1 [k][p][gate]
__device__ float4 g_wB2[PH*PH];                // w_hh1 [k][p][gate]
__device__ float4 g_b1r[PH];                   // b1 [p][gate]
__device__ float  g_woT[VV*JH];                // w_o transposed [v][k]

__device__ float g_h0[BB*PH], g_c0[BB*PH], g_h1[BB*PH], g_c1[BB*PH];
__device__ float g_h0n[BB*PH], g_c0n[BB*PH], g_h1n[BB*PH], g_c1n[BB*PH];
__device__ float g_jrelu[BB*JH];
__device__ int g_pre[BB], g_time[BB], g_olen[BB];
__device__ int g_tok[BB*MAXL];
__device__ unsigned g_eq[NSTEP];               // #batches at eos, per step
__device__ unsigned g_done[NSTEP];             // #CTAs finished phase D, per step
__device__ unsigned g_gcnt[4*32], g_grel[4*32]; // padded: one 128B line per group

__device__ __forceinline__ float sigf(float x){ return 1.0f/(1.0f+expf(-x)); }

// acq/rel monotonic barrier over n CTAs (group-local, padded counters)
__device__ __forceinline__ void barwait(unsigned* cnt, unsigned* rel, unsigned n){
    __syncthreads();
    if (threadIdx.x == 0){
        unsigned a;
        asm volatile("atom.add.release.gpu.global.u32 %0,[%1],1;"
                     : "=r"(a) : "l"(cnt) : "memory");
        a += 1u;
        if (a % n == 0u){
            asm volatile("red.release.gpu.global.max.u32 [%0],%1;"
                         :: "l"(rel), "r"(a) : "memory");
        } else {
            unsigned tgt = ((a + n - 1u)/n)*n;
            unsigned v;
            do {
                asm volatile("ld.acquire.gpu.global.u32 %0,[%1];"
                             : "=r"(v) : "l"(rel) : "memory");
            } while (v < tgt);
        }
    }
    __syncthreads();
}

__device__ __forceinline__ unsigned long long pack64(float lo, float hi){
    unsigned long long r;
    asm("mov.b64 %0,{%1,%2};" : "=l"(r) : "f"(lo), "f"(hi));
    return r;
}
__device__ __forceinline__ void unpack64(unsigned long long v, float& lo, float& hi){
    asm("mov.b64 {%0,%1},%2;" : "=f"(lo), "=f"(hi) : "l"(v));
}
__device__ __forceinline__ void fma2(unsigned long long& acc, unsigned long long a, unsigned long long b){
    asm("fma.rn.f32x2 %0,%1,%2,%0;" : "+l"(acc) : "l"(a), "l"(b));
}

// ---------------- init + weight re-layouts (merged: shifts launch count) ----------------
__global__ void rearr_init_kernel(const float* __restrict__ w_hh0, const float* __restrict__ w_ih1,
                                  const float* __restrict__ w_hh1, const float* __restrict__ b1,
                                  const float* __restrict__ w_o){
    int i = blockIdx.x*256 + threadIdx.x;
    // init
    if (i < BB*PH){ g_h0[i]=0.f; g_c0[i]=0.f; g_h1[i]=0.f; g_c1[i]=0.f; }
    if (i < BB){ g_pre[i]=0; g_time[i]=0; g_olen[i]=0; }
    if (i < BB*MAXL) g_tok[i] = BLANKV;
    if (i < NSTEP){ g_eq[i] = 0u; g_done[i] = 0u; }
    if (i < 4*32){ g_gcnt[i]=0u; g_grel[i]=0u; }
    // weight re-layouts
    const int Nt = PH*PH*4;
    if (i < Nt){
        int g = i & 3, p = (i >> 2) % PH, k = i / (PH*4);
        int src = k*(4*PH) + g*PH + p;
        ((float*)g_wA )[i] = w_hh0[src];
        ((float*)g_wB1)[i] = w_ih1[src];
        ((float*)g_wB2)[i] = w_hh1[src];
    }
    if (i < PH*4){
        int g = i & 3, p = i >> 2;
        ((float*)g_b1r)[i] = b1[g*PH + p];
    }
    if (i < VV*JH){
        int v = i / JH, k = i - v*JH;
        g_woT[i] = w_o[k*VV + v];
    }
}

// ---------------- xg0[v][p][g] = b0 + embed[v,:] @ w_ih0[:,g*PH+p] ----------------
__global__ void xg0_kernel(const float* __restrict__ embed, const float* __restrict__ w_ih0,
                           const float* __restrict__ b0v){
    __shared__ float es[PH];
    int v = blockIdx.x;
    for (int k = threadIdx.x; k < PH; k += 256) es[k] = embed[v*PH + k];
    __syncthreads();
    for (int j = threadIdx.x; j < PH*4; j += 256){
        int p = j >> 2, g = j & 3;
        float a = b0v[g*PH + p];
        const float* w = w_ih0 + g*PH + p;
        for (int k = 0; k < PH; k++) a = fmaf(es[k], w[k*(4*PH)], a);
        ((float*)g_xg0)[v*PH*4 + j] = a;
    }
}

// ---------------- Fproj: double-buffered, transposed-A tiles ----------------
__global__ void __launch_bounds__(256) fproj_kernel(const float* __restrict__ A,
                                                    const float* __restrict__ Bm,
                                                    const float* __restrict__ bj){
    const int N = JH, K = FH;
    __shared__ float Ast[2][16][68];
    __shared__ float Bs [2][16][68];
    int bm = blockIdx.y*64, bn = blockIdx.x*64;
    int tid = threadIdx.x;
    int tx = tid & 15, ty = tid >> 4;
    int lm = tid >> 2, lkq = tid & 3;
    int lk = tid >> 4, lnq = tid & 15;

    float acc[4][4];
#pragma unroll
    for (int i = 0; i < 4; i++)
#pragma unroll
        for (int j = 0; j < 4; j++) acc[i][j] = 0.f;

    float4 va = *(const float4*)(A + (size_t)(bm+lm)*K + lkq*4);
    float4 vb = *(const float4*)(Bm + (size_t)lk*N + bn + lnq*4);
    Ast[0][lkq*4+0][lm]=va.x; Ast[0][lkq*4+1][lm]=va.y;
    Ast[0][lkq*4+2][lm]=va.z; Ast[0][lkq*4+3][lm]=va.w;
    *(float4*)&Bs[0][lk][lnq*4] = vb;
    __syncthreads();

    int buf = 0;
    for (int k0 = 16; k0 < K; k0 += 16){
        va = *(const float4*)(A + (size_t)(bm+lm)*K + k0 + lkq*4);
        vb = *(const float4*)(Bm + (size_t)(k0+lk)*N + bn + lnq*4);
#pragma unroll
        for (int k = 0; k < 16; k++){
            float4 av = *(const float4*)&Ast[buf][k][ty*4];
            float4 bv = *(const float4*)&Bs [buf][k][tx*4];
            acc[0][0]=fmaf(av.x,bv.x,acc[0][0]); acc[0][1]=fmaf(av.x,bv.y,acc[0][1]);
            acc[0][2]=fmaf(av.x,bv.z,acc[0][2]); acc[0][3]=fmaf(av.x,bv.w,acc[0][3]);
            acc[1][0]=fmaf(av.y,bv.x,acc[1][0]); acc[1][1]=fmaf(av.y,bv.y,acc[1][1]);
            acc[1][2]=fmaf(av.y,bv.z,acc[1][2]); acc[1][3]=fmaf(av.y,bv.w,acc[1][3]);
            acc[2][0]=fmaf(av.z,bv.x,acc[2][0]); acc[2][1]=fmaf(av.z,bv.y,acc[2][1]);
            acc[2][2]=fmaf(av.z,bv.z,acc[2][2]); acc[2][3]=fmaf(av.z,bv.w,acc[2][3]);
            acc[3][0]=fmaf(av.w,bv.x,acc[3][0]); acc[3][1]=fmaf(av.w,bv.y,acc[3][1]);
            acc[3][2]=fmaf(av.w,bv.z,acc[3][2]); acc[3][3]=fmaf(av.w,bv.w,acc[3][3]);
        }
        int nb = buf ^ 1;
        Ast[nb][lkq*4+0][lm]=va.x; Ast[nb][lkq*4+1][lm]=va.y;
        Ast[nb][lkq*4+2][lm]=va.z; Ast[nb][lkq*4+3][lm]=va.w;
        *(float4*)&Bs[nb][lk][lnq*4] = vb;
        __syncthreads();
        buf = nb;
    }
#pragma unroll
    for (int k = 0; k < 16; k++){
        float4 av = *(const float4*)&Ast[buf][k][ty*4];
        float4 bv = *(const float4*)&Bs [buf][k][tx*4];
        acc[0][0]=fmaf(av.x,bv.x,acc[0][0]); acc[0][1]=fmaf(av.x,bv.y,acc[0][1]);
        acc[0][2]=fmaf(av.x,bv.z,acc[0][2]); acc[0][3]=fmaf(av.x,bv.w,acc[0][3]);
        acc[1][0]=fmaf(av.y,bv.x,acc[1][0]); acc[1][1]=fmaf(av.y,bv.y,acc[1][1]);
        acc[1][2]=fmaf(av.y,bv.z,acc[1][2]); acc[1][3]=fmaf(av.y,bv.w,acc[1][3]);
        acc[2][0]=fmaf(av.z,bv.x,acc[2][0]); acc[2][1]=fmaf(av.z,bv.y,acc[2][1]);
        acc[2][2]=fmaf(av.z,bv.z,acc[2][2]); acc[2][3]=fmaf(av.z,bv.w,acc[2][3]);
        acc[3][0]=fmaf(av.w,bv.x,acc[3][0]); acc[3][1]=fmaf(av.w,bv.y,acc[3][1]);
        acc[3][2]=fmaf(av.w,bv.z,acc[3][2]); acc[3][3]=fmaf(av.w,bv.w,acc[3][3]);
    }
#pragma unroll
    for (int i = 0; i < 4; i++)
#pragma unroll
        for (int j = 0; j < 4; j++){
            int n = bn + tx*4 + j;
            g_Fproj[(size_t)(bm + ty*4 + i)*N + n] = acc[i][j] + bj[n];
        }
}

// ================= persistent decode: 128 CTAs x 320 threads =================
// SMEM: swA2/swB12/swB22 (3x51200, k-pair packed) + swg2 (20480) + smh (41472) + smy/smnb
#define SW_U2  3200                    // ulonglong2 count per LSTM weight slice (160 k2 x 10 p x 2)
#define HSTR   324                     // %32==4 -> conflict-free LDS.128
#define SMH_F  (32*HSTR)

__global__ void __launch_bounds__(320,1)
decode_kernel(const int* __restrict__ f_lens, const float* __restrict__ w_g,
              const float* __restrict__ b_o,
              float* __restrict__ out, int out_size){
    extern __shared__ float smem[];
    ulonglong2* swA2  = (ulonglong2*)smem;
    ulonglong2* swB12 = swA2  + SW_U2;
    ulonglong2* swB22 = swB12 + SW_U2;
    unsigned long long* swg2 = (unsigned long long*)(swB22 + SW_U2);  // [160 k2][16 j]
    float*  smh  = (float*)(swg2 + 160*16);
    float*  smy  = smh + SMH_F;
    int*    smnb = (int*)(smy + 32);

    const int tid = threadIdx.x;
    const int cta = blockIdx.x;
    const int bb  = cta >> 5;           // batch group 0..3
    const int sub = cta & 31;           // p/j slice 0..31
    const int b0  = bb*32;
    const int lane = tid & 31, wrp = tid >> 5;
    // LSTM lane remap: lane = 2*bl4 + psel; warp = bhalf*5 + pduo
    const int psel = lane & 1, bl4 = lane >> 1;
    const int bhalf = (wrp < 5) ? 0 : 1, pduo = (wrp < 5) ? wrp : wrp - 5;
    const int bat = bhalf*16 + bl4;
    const int lp  = pduo*2 + psel;
    const int p   = sub*10 + lp;
    const int bgl = b0 + bat;
    // phase-C coords
    const int blc = lane, plc = wrp;
    const int bglc = b0 + blc;
    const int myb = cta;

    unsigned* mycnt = &g_gcnt[bb*32];
    unsigned* myrel = &g_grel[bb*32];

    // ---- one-time weight preload: k-pair gate-packed layout ----
    // swX2[(k2*10+q)*2 + s]: s=0 -> gates(0,1) packs {w[2k2][g],w[2k2+1][g]}, s=1 -> gates(2,3)
    for (int i = tid; i < 1600; i += 320){
        int k2 = i/10, q = i - k2*10;
        int s0 = (2*k2)*PH + sub*10 + q, s1 = (2*k2+1)*PH + sub*10 + q;
        float4 a = g_wA[s0],  b = g_wA[s1];
        swA2[i*2+0] = make_ulonglong2(pack64(a.x,b.x), pack64(a.y,b.y));
        swA2[i*2+1] = make_ulonglong2(pack64(a.z,b.z), pack64(a.w,b.w));
        a = g_wB1[s0]; b = g_wB1[s1];
        swB12[i*2+0] = make_ulonglong2(pack64(a.x,b.x), pack64(a.y,b.y));
        swB12[i*2+1] = make_ulonglong2(pack64(a.z,b.z), pack64(a.w,b.w));
        a = g_wB2[s0]; b = g_wB2[s1];
        swB22[i*2+0] = make_ulonglong2(pack64(a.x,b.x), pack64(a.y,b.y));
        swB22[i*2+1] = make_ulonglong2(pack64(a.z,b.z), pack64(a.w,b.w));
    }
    for (int i = tid; i < 160*16; i += 320){
        int k2 = i >> 4, j = i & 15;
        swg2[i] = pack64(w_g[(size_t)(2*k2)*JH + sub*16 + j],
                         w_g[(size_t)(2*k2+1)*JH + sub*16 + j]);
    }
    __syncthreads();

    const ulonglong2* hrow2  = (const ulonglong2*)(smh + bat*HSTR);
    const ulonglong2* hrowc2 = (const ulonglong2*)(smh + blc*HSTR);

    for (int step = 0; step < NSTEP; step++){
        // ============ phase A: LSTM0 ============
#pragma unroll 8
        for (int j = 0; j < 32; j++)
            smh[j*HSTR + tid] = __ldcg(&g_h0[(b0+j)*PH + tid]);
        __syncthreads();
        {
            int pre = __ldcg(&g_pre[bgl]);
            float4 x0 = g_xg0[pre*PH + p];
            unsigned long long a0 = pack64(x0.x, 0.f), a1 = pack64(x0.y, 0.f);
            unsigned long long a2 = pack64(x0.z, 0.f), a3 = pack64(x0.w, 0.f);
#pragma unroll 4
            for (int k4 = 0; k4 < PH/4; k4++){
                ulonglong2 h2 = hrow2[k4];              // k-pairs (4k,4k+1),(4k+2,4k+3)
                int base = k4*40 + lp*2;
                ulonglong2 wa0 = swA2[base+0];
                ulonglong2 wa1 = swA2[base+1];
                ulonglong2 wb0 = swA2[base+20];
                ulonglong2 wb1 = swA2[base+21];
                fma2(a0,h2.x,wa0.x); fma2(a1,h2.x,wa0.y); fma2(a2,h2.x,wa1.x); fma2(a3,h2.x,wa1.y);
                fma2(a0,h2.y,wb0.x); fma2(a1,h2.y,wb0.y); fma2(a2,h2.y,wb1.x); fma2(a3,h2.y,wb1.y);
            }
            float l0,h0v,l1,h1v,l2,h2v,l3,h3v;
            unpack64(a0,l0,h0v); unpack64(a1,l1,h1v); unpack64(a2,l2,h2v); unpack64(a3,l3,h3v);
            float gi=l0+h0v, gf=l1+h1v, gg=l2+h2v, go=l3+h3v;
            float c  = __ldcg(&g_c0[bgl*PH + p]);
            float cn = sigf(gf)*c + sigf(gi)*tanhf(gg);
            float hn = sigf(go)*tanhf(cn);
            __stcg(&g_c0n[bgl*PH + p], cn);
            __stcg(&g_h0n[bgl*PH + p], hn);
        }
        barwait(mycnt, myrel, 32u);

        // ============ phase B: LSTM1 (K = 320 + 320) ============
        {
            float4 bv = g_b1r[p];
            unsigned long long a0 = pack64(bv.x, 0.f), a1 = pack64(bv.y, 0.f);
            unsigned long long a2 = pack64(bv.z, 0.f), a3 = pack64(bv.w, 0.f);
#pragma unroll 1
            for (int pass = 0; pass < 2; pass++){
                const float* hin = pass ? g_h1 : g_h0n;
                const ulonglong2* W = pass ? swB22 : swB12;
#pragma unroll 8
                for (int j = 0; j < 32; j++)
                    smh[j*HSTR + tid] = __ldcg(&hin[(b0+j)*PH + tid]);
                __syncthreads();
#pragma unroll 4
                for (int k4 = 0; k4 < PH/4; k4++){
                    ulonglong2 h2 = hrow2[k4];
                    int base = k4*40 + lp*2;
                    ulonglong2 wa0 = W[base+0];
                    ulonglong2 wa1 = W[base+1];
                    ulonglong2 wb0 = W[base+20];
                    ulonglong2 wb1 = W[base+21];
                    fma2(a0,h2.x,wa0.x); fma2(a1,h2.x,wa0.y); fma2(a2,h2.x,wa1.x); fma2(a3,h2.x,wa1.y);
                    fma2(a0,h2.y,wb0.x); fma2(a1,h2.y,wb0.y); fma2(a2,h2.y,wb1.x); fma2(a3,h2.y,wb1.y);
                }
                __syncthreads();
            }
            float l0,h0v,l1,h1v,l2,h2v,l3,h3v;
            unpack64(a0,l0,h0v); unpack64(a1,l1,h1v); unpack64(a2,l2,h2v); unpack64(a3,l3,h3v);
            float gi=l0+h0v, gf=l1+h1v, gg=l2+h2v, go=l3+h3v;
            float c  = __ldcg(&g_c1[bgl*PH + p]);
            float cn = sigf(gf)*c + sigf(gi)*tanhf(gg);
            float hn = sigf(go)*tanhf(cn);
            __stcg(&g_c1n[bgl*PH + p], cn);
            __stcg(&g_h1n[bgl*PH + p], hn);
        }
        barwait(mycnt, myrel, 32u);

        // ============ phase C: jrelu = relu(Fproj[time[b]] + h1n @ w_g) ============
        {
#pragma unroll 8
            for (int j = 0; j < 32; j++)
                smh[j*HSTR + tid] = __ldcg(&g_h1n[(b0+j)*PH + tid]);
            __syncthreads();
            unsigned long long p1 = 0ull, p2 = 0ull;
#pragma unroll 4
            for (int k4 = 0; k4 < PH/4; k4++){
                ulonglong2 h2 = hrowc2[k4];
                unsigned long long w00 = swg2[(2*k4+0)*16 + plc];
                unsigned long long w01 = swg2[(2*k4+1)*16 + plc];
                fma2(p1, h2.x, w00); fma2(p1, h2.y, w01);
                if (plc < 6){
                    unsigned long long w10 = swg2[(2*k4+0)*16 + plc + 10];
                    unsigned long long w11 = swg2[(2*k4+1)*16 + plc + 10];
                    fma2(p2, h2.x, w10); fma2(p2, h2.y, w11);
                }
            }
            float lo, hi;
            unpack64(p1, lo, hi);
            float acc1 = lo + hi;
            int t = __ldcg(&g_time[bglc]);
            size_t fb = ((size_t)t*BB + bglc)*JH + sub*16;
            float r1 = __ldcg(&g_Fproj[fb + plc]) + acc1;
            __stcg(&g_jrelu[bglc*JH + sub*16 + plc], r1 > 0.f ? r1 : 0.f);
            if (plc < 6){
                unpack64(p2, lo, hi);
                float r2 = __ldcg(&g_Fproj[fb + plc + 10]) + (lo + hi);
                __stcg(&g_jrelu[bglc*JH + sub*16 + plc + 10], r2 > 0.f ? r2 : 0.f);
            }
        }
        barwait(mycnt, myrel, 32u);

        // ============ phase D: logits + argmax + commit (CTA = batch) ============
        {
            __syncthreads();
            for (int e = tid; e < JH; e += 320)
                smh[e] = __ldcg(&g_jrelu[myb*JH + e]);
            __syncthreads();
#pragma unroll
            for (int vi = 0; vi < 3; vi++){
                int v = wrp + vi*10;
                if (v < VV){
                    float a = 0.f;
#pragma unroll
                    for (int k = lane; k < JH; k += 32)
                        a = fmaf(smh[k], __ldcg(&g_woT[v*JH + k]), a);
#pragma unroll
                    for (int off = 16; off > 0; off >>= 1)
                        a += __shfl_xor_sync(0xffffffffu, a, off);
                    if (lane == 0) smy[v] = a + b_o[v];
                }
            }
            __syncthreads();
            if (tid < VV){
                int idx = (step*BB + myb)*VV + tid;
                if (idx < out_size) out[idx] = smy[tid];
            }
            if (tid == 0){
                int sym = 0; float best = smy[0];
                for (int v = 1; v < VV; v++) if (smy[v] > best){ best = smy[v]; sym = v; }
                int fin = 0;
                if (step > 0){
                    unsigned d;
                    do {
                        asm volatile("ld.acquire.gpu.global.u32 %0,[%1];"
                                     : "=r"(d) : "l"(&g_done[step-1]) : "memory");
                    } while (d < (unsigned)BB);
                    fin = (__ldcg(&g_eq[step-1]) == (unsigned)BB);
                }
                int nb  = (!fin) && (sym != BLANKV);
                int blk = (!fin) && (sym == BLANKV);
                if (nb){
                    int olen = g_olen[myb];
                    int pos = olen < (MAXL-1) ? olen : (MAXL-1);
                    g_tok[myb*MAXL + pos] = sym;
                    g_olen[myb] = olen + 1;
                    __stcg(&g_pre[myb], sym);
                }
                int tm  = __ldcg(&g_time[myb]);
                int eos = f_lens[myb] - 1;
                if (blk){ tm = tm + 1; if (tm > eos) tm = eos; }
                __stcg(&g_time[myb], tm);
                if (tm == eos) atomicAdd(&g_eq[step], 1u);
                unsigned du;
                asm volatile("atom.add.release.gpu.global.u32 %0,[%1],1;"
                             : "=r"(du) : "l"(&g_done[step]) : "memory");
                *smnb = nb;
            }
            __syncthreads();
            if (*smnb){
                int i = myb*PH + tid;
                __stcg(&g_h0[i], __ldcg(&g_h0n[i]));
                __stcg(&g_c0[i], __ldcg(&g_c0n[i]));
                __stcg(&g_h1[i], __ldcg(&g_h1n[i]));
                __stcg(&g_c1[i], __ldcg(&g_c1n[i]));
            }
        }
        barwait(mycnt, myrel, 32u);   // group-local step boundary
    }

    // final: tokens + out_lens (cast to float), CTA = batch
    if (tid < MAXL){
        int idx = YSN + myb*MAXL + tid;
        if (idx < out_size) out[idx] = (float)g_tok[myb*MAXL + tid];
    }
    if (tid == 0){
        int idx = YSN + BB*MAXL + myb;
        if (idx < out_size) out[idx] = (float)g_olen[myb];
    }
}

extern "C" void kernel_launch(void* const* d_in, const int* in_sizes, int n_in,
                              void* d_out, int out_size){
    const float* f      = (const float*)d_in[0];
    const int*   f_lens = (const int*)  d_in[1];
    const float* embed  = (const float*)d_in[2];
    const float* w_ih0  = (const float*)d_in[3];
    const float* w_hh0  = (const float*)d_in[4];
    const float* b0     = (const float*)d_in[5];
    const float* w_ih1  = (const float*)d_in[6];
    const float* w_hh1  = (const float*)d_in[7];
    const float* b1     = (const float*)d_in[8];
    const float* w_f    = (const float*)d_in[9];
    const float* w_g    = (const float*)d_in[10];
    const float* b_j    = (const float*)d_in[11];
    const float* w_o    = (const float*)d_in[12];
    const float* b_o    = (const float*)d_in[13];
    float* out = (float*)d_out;

    const int smem_bytes = 3*51200 + 20480 + SMH_F*4 + 256;
    cudaFuncSetAttribute(decode_kernel, cudaFuncAttributeMaxDynamicSharedMemorySize, smem_bytes);

    rearr_init_kernel<<<1600, 256>>>(w_hh0, w_ih1, w_hh1, b1, w_o);
    xg0_kernel<<<VV, 256>>>(embed, w_ih0, b0);
    fproj_kernel<<<dim3(JH/64, (TT*BB)/64), 256>>>(f, w_f, b_j);
    decode_kernel<<<BB, 320, smem_bytes>>>(f_lens, w_g, b_o, out, out_size);
}

// round 11
// speedup vs baseline: 1.6719x; 1.0161x over previous
#include <cuda_runtime.h>
#include <math.h>

#define TT 200
#define BB 128
#define FH 1024
#define PH 320
#define JH 512
#define VV 29
#define BLANKV 28
#define NSTEP 400
#define MAXL 256
#define YSN (NSTEP*BB*VV)
#define THR 640

// ---------------- device scratch (no runtime allocation) ----------------
__device__ float  g_Fproj[(size_t)TT*BB*JH];   // f @ w_f + b_j
__device__ float4 g_xg0[VV*PH];                // embed@w_ih0+b0, [v][p][gate]
__device__ float4 g_wA [PH*PH];                // w_hh0 [k][p][gate]
__device__ float4 g_wB1[PH*PH];                // w_ih1 [k][p][gate]
__device__ float4 g_wB2[PH*PH];                // w_hh1 [k][p][gate]
__device__ float4 g_b1r[PH];                   // b1 [p][gate]
__device__ float  g_woT[VV*JH];                // w_o transposed [v][k]

__device__ float g_h0[BB*PH], g_c0[BB*PH], g_h1[BB*PH], g_c1[BB*PH];
__device__ float g_h0n[BB*PH], g_c0n[BB*PH], g_h1n[BB*PH], g_c1n[BB*PH];
__device__ float g_jrelu[BB*JH];
__device__ int g_pre[BB], g_time[BB], g_olen[BB];
__device__ int g_tok[BB*MAXL];
__device__ unsigned g_eq[NSTEP];               // #batches at eos, per step
__device__ unsigned g_done[NSTEP];             // #CTAs finished phase D, per step
__device__ unsigned g_gcnt[4*32], g_grel[4*32]; // one 128B line per group

__device__ __forceinline__ float sigf(float x){ return 1.0f/(1.0f+expf(-x)); }

// acq/rel monotonic barrier over n CTAs (group-local, padded counters)
__device__ __forceinline__ void barwait(unsigned* cnt, unsigned* rel, unsigned n){
    __syncthreads();
    if (threadIdx.x == 0){
        unsigned a;
        asm volatile("atom.add.release.gpu.global.u32 %0,[%1],1;"
                     : "=r"(a) : "l"(cnt) : "memory");
        a += 1u;
        if (a % n == 0u){
            asm volatile("red.release.gpu.global.max.u32 [%0],%1;"
                         :: "l"(rel), "r"(a) : "memory");
        } else {
            unsigned tgt = ((a + n - 1u)/n)*n;
            unsigned v;
            do {
                asm volatile("ld.acquire.gpu.global.u32 %0,[%1];"
                             : "=r"(v) : "l"(rel) : "memory");
            } while (v < tgt);
        }
    }
    __syncthreads();
}

__device__ __forceinline__ unsigned long long pack64(float lo, float hi){
    unsigned long long r;
    asm("mov.b64 %0,{%1,%2};" : "=l"(r) : "f"(lo), "f"(hi));
    return r;
}
__device__ __forceinline__ void unpack64(unsigned long long v, float& lo, float& hi){
    asm("mov.b64 {%0,%1},%2;" : "=f"(lo), "=f"(hi) : "l"(v));
}
__device__ __forceinline__ void fma2(unsigned long long& acc, unsigned long long a, unsigned long long b){
    asm("fma.rn.f32x2 %0,%1,%2,%0;" : "+l"(acc) : "l"(a), "l"(b));
}
__device__ __forceinline__ void add2(unsigned long long& acc, unsigned long long a){
    asm("add.rn.f32x2 %0,%0,%1;" : "+l"(acc) : "l"(a));
}

// ---------------- init + weight re-layouts ----------------
__global__ void rearr_init_kernel(const float* __restrict__ w_hh0, const float* __restrict__ w_ih1,
                                  const float* __restrict__ w_hh1, const float* __restrict__ b1,
                                  const float* __restrict__ w_o){
    int i = blockIdx.x*256 + threadIdx.x;
    if (i < BB*PH){ g_h0[i]=0.f; g_c0[i]=0.f; g_h1[i]=0.f; g_c1[i]=0.f; }
    if (i < BB){ g_pre[i]=0; g_time[i]=0; g_olen[i]=0; }
    if (i < BB*MAXL) g_tok[i] = BLANKV;
    if (i < NSTEP){ g_eq[i] = 0u; g_done[i] = 0u; }
    if (i < 4*32){ g_gcnt[i]=0u; g_grel[i]=0u; }
    const int Nt = PH*PH*4;
    if (i < Nt){
        int g = i & 3, p = (i >> 2) % PH, k = i / (PH*4);
        int src = k*(4*PH) + g*PH + p;
        ((float*)g_wA )[i] = w_hh0[src];
        ((float*)g_wB1)[i] = w_ih1[src];
        ((float*)g_wB2)[i] = w_hh1[src];
    }
    if (i < PH*4){
        int g = i & 3, p = i >> 2;
        ((float*)g_b1r)[i] = b1[g*PH + p];
    }
    if (i < VV*JH){
        int v = i / JH, k = i - v*JH;
        g_woT[i] = w_o[k*VV + v];
    }
}

// ---------------- xg0[v][p][g] = b0 + embed[v,:] @ w_ih0[:,g*PH+p] ----------------
__global__ void xg0_kernel(const float* __restrict__ embed, const float* __restrict__ w_ih0,
                           const float* __restrict__ b0v){
    __shared__ float es[PH];
    int v = blockIdx.x;
    for (int k = threadIdx.x; k < PH; k += 256) es[k] = embed[v*PH + k];
    __syncthreads();
    for (int j = threadIdx.x; j < PH*4; j += 256){
        int p = j >> 2, g = j & 3;
        float a = b0v[g*PH + p];
        const float* w = w_ih0 + g*PH + p;
        for (int k = 0; k < PH; k++) a = fmaf(es[k], w[k*(4*PH)], a);
        ((float*)g_xg0)[v*PH*4 + j] = a;
    }
}

// ---------------- Fproj: double-buffered, transposed-A tiles ----------------
__global__ void __launch_bounds__(256) fproj_kernel(const float* __restrict__ A,
                                                    const float* __restrict__ Bm,
                                                    const float* __restrict__ bj){
    const int N = JH, K = FH;
    __shared__ float Ast[2][16][68];
    __shared__ float Bs [2][16][68];
    int bm = blockIdx.y*64, bn = blockIdx.x*64;
    int tid = threadIdx.x;
    int tx = tid & 15, ty = tid >> 4;
    int lm = tid >> 2, lkq = tid & 3;
    int lk = tid >> 4, lnq = tid & 15;

    float acc[4][4];
#pragma unroll
    for (int i = 0; i < 4; i++)
#pragma unroll
        for (int j = 0; j < 4; j++) acc[i][j] = 0.f;

    float4 va = *(const float4*)(A + (size_t)(bm+lm)*K + lkq*4);
    float4 vb = *(const float4*)(Bm + (size_t)lk*N + bn + lnq*4);
    Ast[0][lkq*4+0][lm]=va.x; Ast[0][lkq*4+1][lm]=va.y;
    Ast[0][lkq*4+2][lm]=va.z; Ast[0][lkq*4+3][lm]=va.w;
    *(float4*)&Bs[0][lk][lnq*4] = vb;
    __syncthreads();

    int buf = 0;
    for (int k0 = 16; k0 < K; k0 += 16){
        va = *(const float4*)(A + (size_t)(bm+lm)*K + k0 + lkq*4);
        vb = *(const float4*)(Bm + (size_t)(k0+lk)*N + bn + lnq*4);
#pragma unroll
        for (int k = 0; k < 16; k++){
            float4 av = *(const float4*)&Ast[buf][k][ty*4];
            float4 bv = *(const float4*)&Bs [buf][k][tx*4];
            acc[0][0]=fmaf(av.x,bv.x,acc[0][0]); acc[0][1]=fmaf(av.x,bv.y,acc[0][1]);
            acc[0][2]=fmaf(av.x,bv.z,acc[0][2]); acc[0][3]=fmaf(av.x,bv.w,acc[0][3]);
            acc[1][0]=fmaf(av.y,bv.x,acc[1][0]); acc[1][1]=fmaf(av.y,bv.y,acc[1][1]);
            acc[1][2]=fmaf(av.y,bv.z,acc[1][2]); acc[1][3]=fmaf(av.y,bv.w,acc[1][3]);
            acc[2][0]=fmaf(av.z,bv.x,acc[2][0]); acc[2][1]=fmaf(av.z,bv.y,acc[2][1]);
            acc[2][2]=fmaf(av.z,bv.z,acc[2][2]); acc[2][3]=fmaf(av.z,bv.w,acc[2][3]);
            acc[3][0]=fmaf(av.w,bv.x,acc[3][0]); acc[3][1]=fmaf(av.w,bv.y,acc[3][1]);
            acc[3][2]=fmaf(av.w,bv.z,acc[3][2]); acc[3][3]=fmaf(av.w,bv.w,acc[3][3]);
        }
        int nb = buf ^ 1;
        Ast[nb][lkq*4+0][lm]=va.x; Ast[nb][lkq*4+1][lm]=va.y;
        Ast[nb][lkq*4+2][lm]=va.z; Ast[nb][lkq*4+3][lm]=va.w;
        *(float4*)&Bs[nb][lk][lnq*4] = vb;
        __syncthreads();
        buf = nb;
    }
#pragma unroll
    for (int k = 0; k < 16; k++){
        float4 av = *(const float4*)&Ast[buf][k][ty*4];
        float4 bv = *(const float4*)&Bs [buf][k][tx*4];
        acc[0][0]=fmaf(av.x,bv.x,acc[0][0]); acc[0][1]=fmaf(av.x,bv.y,acc[0][1]);
        acc[0][2]=fmaf(av.x,bv.z,acc[0][2]); acc[0][3]=fmaf(av.x,bv.w,acc[0][3]);
        acc[1][0]=fmaf(av.y,bv.x,acc[1][0]); acc[1][1]=fmaf(av.y,bv.y,acc[1][1]);
        acc[1][2]=fmaf(av.y,bv.z,acc[1][2]); acc[1][3]=fmaf(av.y,bv.w,acc[1][3]);
        acc[2][0]=fmaf(av.z,bv.x,acc[2][0]); acc[2][1]=fmaf(av.z,bv.y,acc[2][1]);
        acc[2][2]=fmaf(av.z,bv.z,acc[2][2]); acc[2][3]=fmaf(av.z,bv.w,acc[2][3]);
        acc[3][0]=fmaf(av.w,bv.x,acc[3][0]); acc[3][1]=fmaf(av.w,bv.y,acc[3][1]);
        acc[3][2]=fmaf(av.w,bv.z,acc[3][2]); acc[3][3]=fmaf(av.w,bv.w,acc[3][3]);
    }
#pragma unroll
    for (int i = 0; i < 4; i++)
#pragma unroll
        for (int j = 0; j < 4; j++){
            int n = bn + tx*4 + j;
            g_Fproj[(size_t)(bm + ty*4 + i)*N + n] = acc[i][j] + bj[n];
        }
}

// ================= persistent decode: 128 CTAs x 640 threads =================
#define SW_U2  3200
#define HSTR   324                     // %32==4 -> conflict-free LDS.128
#define SMH_F  (32*HSTR)

__global__ void __launch_bounds__(THR,1)
decode_kernel(const int* __restrict__ f_lens, const float* __restrict__ w_g,
              const float* __restrict__ b_o,
              float* __restrict__ out, int out_size){
    extern __shared__ float smem[];
    ulonglong2* swA2  = (ulonglong2*)smem;
    ulonglong2* swB12 = swA2  + SW_U2;
    ulonglong2* swB22 = swB12 + SW_U2;
    unsigned long long* swg2 = (unsigned long long*)(swB22 + SW_U2);  // [160 k2][16 j]
    float*  smh   = (float*)(swg2 + 160*16);
    ulonglong2* ppart = (ulonglong2*)(smh + SMH_F);   // 320*2 entries (10 KB)
    float*  smy   = (float*)(ppart + 640);
    int*    smnb  = (int*)(smy + 32);

    const int tid = threadIdx.x;
    const int cta = blockIdx.x;
    const int bb  = cta >> 5;           // batch group 0..3
    const int sub = cta & 31;           // p/j slice 0..31
    const int b0  = bb*32;
    const int lane = tid & 31, wrp = tid >> 5;   // 0..19
    const int khalf = (tid >= 320);
    const int tidp  = khalf ? tid - 320 : tid;   // 0..319
    const int wrpp  = tidp >> 5;                 // 0..9
    // LSTM remap on tidp: lane = 2*bl4 + psel; warp' = bhalf*5 + pduo
    const int psel = lane & 1, bl4 = lane >> 1;
    const int bhalf = (wrpp < 5) ? 0 : 1, pduo = (wrpp < 5) ? wrpp : wrpp - 5;
    const int bat = bhalf*16 + bl4;
    const int lp  = pduo*2 + psel;
    const int p   = sub*10 + lp;
    const int bgl = b0 + bat;
    // phase-C coords: 512 active threads
    const int blc = lane, plc = wrp;             // plc 0..15 valid
    const int bglc = b0 + blc;
    const int myb = cta;

    unsigned* mycnt = &g_gcnt[bb*32];
    unsigned* myrel = &g_grel[bb*32];

    // ---- one-time weight preload: k-pair gate-packed layout ----
    for (int i = tid; i < 1600; i += THR){
        int k2 = i/10, q = i - k2*10;
        int s0 = (2*k2)*PH + sub*10 + q, s1 = (2*k2+1)*PH + sub*10 + q;
        float4 a = g_wA[s0],  b = g_wA[s1];
        swA2[i*2+0] = make_ulonglong2(pack64(a.x,b.x), pack64(a.y,b.y));
        swA2[i*2+1] = make_ulonglong2(pack64(a.z,b.z), pack64(a.w,b.w));
        a = g_wB1[s0]; b = g_wB1[s1];
        swB12[i*2+0] = make_ulonglong2(pack64(a.x,b.x), pack64(a.y,b.y));
        swB12[i*2+1] = make_ulonglong2(pack64(a.z,b.z), pack64(a.w,b.w));
        a = g_wB2[s0]; b = g_wB2[s1];
        swB22[i*2+0] = make_ulonglong2(pack64(a.x,b.x), pack64(a.y,b.y));
        swB22[i*2+1] = make_ulonglong2(pack64(a.z,b.z), pack64(a.w,b.w));
    }
    for (int i = tid; i < 160*16; i += THR){
        int k2 = i >> 4, j = i & 15;
        swg2[i] = pack64(w_g[(size_t)(2*k2)*JH + sub*16 + j],
                         w_g[(size_t)(2*k2+1)*JH + sub*16 + j]);
    }
    __syncthreads();

    const ulonglong2* hrow2  = (const ulonglong2*)(smh + bat*HSTR);
    const ulonglong2* hrowc2 = (const ulonglong2*)(smh + blc*HSTR);
    const int k4beg = khalf*40, k4end = khalf*40 + 40;

    for (int step = 0; step < NSTEP; step++){
        // ============ phase A: LSTM0 (k-split over 2 thread halves) ============
        for (int e = tid; e < 32*PH; e += THR){
            int j = e/PH, k = e - j*PH;
            smh[j*HSTR + k] = __ldcg(&g_h0[(b0+j)*PH + k]);
        }
        __syncthreads();
        {
            unsigned long long a0, a1, a2, a3;
            if (!khalf){
                int pre = __ldcg(&g_pre[bgl]);
                float4 x0 = g_xg0[pre*PH + p];
                a0 = pack64(x0.x,0.f); a1 = pack64(x0.y,0.f);
                a2 = pack64(x0.z,0.f); a3 = pack64(x0.w,0.f);
            } else { a0 = a1 = a2 = a3 = 0ull; }
#pragma unroll 4
            for (int k4 = k4beg; k4 < k4end; k4++){
                ulonglong2 h2 = hrow2[k4];
                int base = k4*40 + lp*2;
                ulonglong2 wa0 = swA2[base+0];
                ulonglong2 wa1 = swA2[base+1];
                ulonglong2 wb0 = swA2[base+20];
                ulonglong2 wb1 = swA2[base+21];
                fma2(a0,h2.x,wa0.x); fma2(a1,h2.x,wa0.y); fma2(a2,h2.x,wa1.x); fma2(a3,h2.x,wa1.y);
                fma2(a0,h2.y,wb0.x); fma2(a1,h2.y,wb0.y); fma2(a2,h2.y,wb1.x); fma2(a3,h2.y,wb1.y);
            }
            if (khalf){
                ppart[tidp*2+0] = make_ulonglong2(a0, a1);
                ppart[tidp*2+1] = make_ulonglong2(a2, a3);
            }
            __syncthreads();
            if (!khalf){
                ulonglong2 q0 = ppart[tidp*2+0], q1 = ppart[tidp*2+1];
                add2(a0, q0.x); add2(a1, q0.y); add2(a2, q1.x); add2(a3, q1.y);
                float l0,h0v,l1,h1v,l2,h2v,l3,h3v;
                unpack64(a0,l0,h0v); unpack64(a1,l1,h1v); unpack64(a2,l2,h2v); unpack64(a3,l3,h3v);
                float gi=l0+h0v, gf=l1+h1v, gg=l2+h2v, go=l3+h3v;
                float c  = __ldcg(&g_c0[bgl*PH + p]);
                float cn = sigf(gf)*c + sigf(gi)*tanhf(gg);
                float hn = sigf(go)*tanhf(cn);
                __stcg(&g_c0n[bgl*PH + p], cn);
                __stcg(&g_h0n[bgl*PH + p], hn);
            }
        }
        // NOTE: no barrier here — A-completion barrier is deferred to mid-B.

        // ============ phase B: LSTM1; pass0 (old h1) needs no barrier ============
        {
            unsigned long long a0, a1, a2, a3;
            if (!khalf){
                float4 bv = g_b1r[p];
                a0 = pack64(bv.x,0.f); a1 = pack64(bv.y,0.f);
                a2 = pack64(bv.z,0.f); a3 = pack64(bv.w,0.f);
            } else { a0 = a1 = a2 = a3 = 0ull; }

            // ---- pass 0: h = g_h1 (previous step state), W = w_hh1 ----
            __syncthreads();   // smh reuse: phase-A readers done (combine sync passed)
            for (int e = tid; e < 32*PH; e += THR){
                int j = e/PH, k = e - j*PH;
                smh[j*HSTR + k] = __ldcg(&g_h1[(b0+j)*PH + k]);
            }
            __syncthreads();
#pragma unroll 4
            for (int k4 = k4beg; k4 < k4end; k4++){
                ulonglong2 h2 = hrow2[k4];
                int base = k4*40 + lp*2;
                ulonglong2 wa0 = swB22[base+0];
                ulonglong2 wa1 = swB22[base+1];
                ulonglong2 wb0 = swB22[base+20];
                ulonglong2 wb1 = swB22[base+21];
                fma2(a0,h2.x,wa0.x); fma2(a1,h2.x,wa0.y); fma2(a2,h2.x,wa1.x); fma2(a3,h2.x,wa1.y);
                fma2(a0,h2.y,wb0.x); fma2(a1,h2.y,wb0.y); fma2(a2,h2.y,wb1.x); fma2(a3,h2.y,wb1.y);
            }

            // ---- deferred A-completion barrier (wait should be ~free by now) ----
            barwait(mycnt, myrel, 32u);

            // ---- pass 1: h = g_h0n, W = w_ih1 ----
            for (int e = tid; e < 32*PH; e += THR){
                int j = e/PH, k = e - j*PH;
                smh[j*HSTR + k] = __ldcg(&g_h0n[(b0+j)*PH + k]);
            }
            __syncthreads();
#pragma unroll 4
            for (int k4 = k4beg; k4 < k4end; k4++){
                ulonglong2 h2 = hrow2[k4];
                int base = k4*40 + lp*2;
                ulonglong2 wa0 = swB12[base+0];
                ulonglong2 wa1 = swB12[base+1];
                ulonglong2 wb0 = swB12[base+20];
                ulonglong2 wb1 = swB12[base+21];
                fma2(a0,h2.x,wa0.x); fma2(a1,h2.x,wa0.y); fma2(a2,h2.x,wa1.x); fma2(a3,h2.x,wa1.y);
                fma2(a0,h2.y,wb0.x); fma2(a1,h2.y,wb0.y); fma2(a2,h2.y,wb1.x); fma2(a3,h2.y,wb1.y);
            }
            if (khalf){
                ppart[tidp*2+0] = make_ulonglong2(a0, a1);
                ppart[tidp*2+1] = make_ulonglong2(a2, a3);
            }
            __syncthreads();
            if (!khalf){
                ulonglong2 q0 = ppart[tidp*2+0], q1 = ppart[tidp*2+1];
                add2(a0, q0.x); add2(a1, q0.y); add2(a2, q1.x); add2(a3, q1.y);
                float l0,h0v,l1,h1v,l2,h2v,l3,h3v;
                unpack64(a0,l0,h0v); unpack64(a1,l1,h1v); unpack64(a2,l2,h2v); unpack64(a3,l3,h3v);
                float gi=l0+h0v, gf=l1+h1v, gg=l2+h2v, go=l3+h3v;
                float c  = __ldcg(&g_c1[bgl*PH + p]);
                float cn = sigf(gf)*c + sigf(gi)*tanhf(gg);
                float hn = sigf(go)*tanhf(cn);
                __stcg(&g_c1n[bgl*PH + p], cn);
                __stcg(&g_h1n[bgl*PH + p], hn);
            }
        }
        barwait(mycnt, myrel, 32u);

        // ============ phase C: jrelu = relu(Fproj[time[b]] + h1n @ w_g) ============
        {
            for (int e = tid; e < 32*PH; e += THR){
                int j = e/PH, k = e - j*PH;
                smh[j*HSTR + k] = __ldcg(&g_h1n[(b0+j)*PH + k]);
            }
            __syncthreads();
            if (plc < 16){
                unsigned long long p1 = 0ull;
#pragma unroll 4
                for (int k4 = 0; k4 < PH/4; k4++){
                    ulonglong2 h2 = hrowc2[k4];
                    fma2(p1, h2.x, swg2[(2*k4+0)*16 + plc]);
                    fma2(p1, h2.y, swg2[(2*k4+1)*16 + plc]);
                }
                float lo, hi;
                unpack64(p1, lo, hi);
                int t = __ldcg(&g_time[bglc]);
                size_t fb = ((size_t)t*BB + bglc)*JH + sub*16;
                float r1 = __ldcg(&g_Fproj[fb + plc]) + (lo + hi);
                __stcg(&g_jrelu[bglc*JH + sub*16 + plc], r1 > 0.f ? r1 : 0.f);
            }
        }
        barwait(mycnt, myrel, 32u);

        // ============ phase D: logits + argmax + commit (CTA = batch) ============
        {
            for (int e = tid; e < JH; e += THR)
                smh[e] = __ldcg(&g_jrelu[myb*JH + e]);
            __syncthreads();
#pragma unroll
            for (int vi = 0; vi < 2; vi++){
                int v = wrp + vi*20;
                if (v < VV){
                    float a = 0.f;
#pragma unroll
                    for (int k = lane; k < JH; k += 32)
                        a = fmaf(smh[k], __ldcg(&g_woT[v*JH + k]), a);
#pragma unroll
                    for (int off = 16; off > 0; off >>= 1)
                        a += __shfl_xor_sync(0xffffffffu, a, off);
                    if (lane == 0) smy[v] = a + b_o[v];
                }
            }
            __syncthreads();
            if (tid < VV){
                int idx = (step*BB + myb)*VV + tid;
                if (idx < out_size) out[idx] = smy[tid];
            }
            if (tid == 0){
                int sym = 0; float best = smy[0];
                for (int v = 1; v < VV; v++) if (smy[v] > best){ best = smy[v]; sym = v; }
                int fin = 0;
                if (step > 0){
                    unsigned d;
                    do {
                        asm volatile("ld.acquire.gpu.global.u32 %0,[%1];"
                                     : "=r"(d) : "l"(&g_done[step-1]) : "memory");
                    } while (d < (unsigned)BB);
                    fin = (__ldcg(&g_eq[step-1]) == (unsigned)BB);
                }
                int nb  = (!fin) && (sym != BLANKV);
                int blk = (!fin) && (sym == BLANKV);
                if (nb){
                    int olen = g_olen[myb];
                    int pos = olen < (MAXL-1) ? olen : (MAXL-1);
                    g_tok[myb*MAXL + pos] = sym;
                    g_olen[myb] = olen + 1;
                    __stcg(&g_pre[myb], sym);
                }
                int tm  = __ldcg(&g_time[myb]);
                int eos = f_lens[myb] - 1;
                if (blk){ tm = tm + 1; if (tm > eos) tm = eos; }
                __stcg(&g_time[myb], tm);
                if (tm == eos) atomicAdd(&g_eq[step], 1u);
                unsigned du;
                asm volatile("atom.add.release.gpu.global.u32 %0,[%1],1;"
                             : "=r"(du) : "l"(&g_done[step]) : "memory");
                *smnb = nb;
            }
            __syncthreads();
            if (*smnb && tid < PH){
                int i = myb*PH + tid;
                __stcg(&g_h0[i], __ldcg(&g_h0n[i]));
                __stcg(&g_c0[i], __ldcg(&g_c0n[i]));
                __stcg(&g_h1[i], __ldcg(&g_h1n[i]));
                __stcg(&g_c1[i], __ldcg(&g_c1n[i]));
            }
        }
        barwait(mycnt, myrel, 32u);   // step boundary (group-local)
    }

    // final: tokens + out_lens (cast to float), CTA = batch
    if (tid < MAXL){
        int idx = YSN + myb*MAXL + tid;
        if (idx < out_size) out[idx] = (float)g_tok[myb*MAXL + tid];
    }
    if (tid == 0){
        int idx = YSN + BB*MAXL + myb;
        if (idx < out_size) out[idx] = (float)g_olen[myb];
    }
}

extern "C" void kernel_launch(void* const* d_in, const int* in_sizes, int n_in,
                              void* d_out, int out_size){
    const float* f      = (const float*)d_in[0];
    const int*   f_lens = (const int*)  d_in[1];
    const float* embed  = (const float*)d_in[2];
    const float* w_ih0  = (const float*)d_in[3];
    const float* w_hh0  = (const float*)d_in[4];
    const float* b0     = (const float*)d_in[5];
    const float* w_ih1  = (const float*)d_in[6];
    const float* w_hh1  = (const float*)d_in[7];
    const float* b1     = (const float*)d_in[8];
    const float* w_f    = (const float*)d_in[9];
    const float* w_g    = (const float*)d_in[10];
    const float* b_j    = (const float*)d_in[11];
    const float* w_o    = (const float*)d_in[12];
    const float* b_o    = (const float*)d_in[13];
    float* out = (float*)d_out;

    // 153600 (3 LSTM slices) + 20480 (wg) + 41472 (smh) + 10240 (ppart) + 256
    const int smem_bytes = 3*51200 + 20480 + SMH_F*4 + 640*16 + 256;
    cudaFuncSetAttribute(decode_kernel, cudaFuncAttributeMaxDynamicSharedMemorySize, smem_bytes);

    rearr_init_kernel<<<1600, 256>>>(w_hh0, w_ih1, w_hh1, b1, w_o);
    xg0_kernel<<<VV, 256>>>(embed, w_ih0, b0);
    fproj_kernel<<<dim3(JH/64, (TT*BB)/64), 256>>>(f, w_f, b_j);
    decode_kernel<<<BB, THR, smem_bytes>>>(f_lens, w_g, b_o, out, out_size);
}